// round 4
// baseline (speedup 1.0000x reference)
#include <cuda_runtime.h>
#include <cstdint>
#include <cfloat>

#define LEVELS 2
#define BATCH  16
#define DIM    256
#define TLEN   2048
#define NPTS   (BATCH * TLEN)       // 32768 points per level
#define KCODES 1024
#define NELEM  (BATCH * DIM * TLEN) // 8388608 per level
#define GATHER_BLOCKS (BATCH * (TLEN / 32))
#define TAU_S  0.01f                // s-space gap == 0.02 distance gap (R2-validated)

// ---------------- scratch (no allocations allowed) ----------------
__device__ float2 g_adup[(size_t)LEVELS * DIM * NPTS];     // A duplicated, d-major: [lvl][d][p] -> (a,a)
__device__ float  g_bt[(size_t)LEVELS * DIM * KCODES];     // codebook transposed: [lvl][d][c]
__device__ float2 g_cninit[LEVELS * (KCODES / 2)];         // packed (-cn/2) pairs
__device__ float  g_partial[LEVELS][GATHER_BLOCKS];
__device__ int    g_idx[LEVELS][NPTS];
__device__ int    g_refine_count[LEVELS];
__device__ int    g_refine_list[LEVELS][NPTS];

// ---------------- f32x2 / async helpers ----------------
__device__ __forceinline__ void fma2(unsigned long long& acc,
                                     unsigned long long a,
                                     unsigned long long b) {
    asm("fma.rn.f32x2 %0, %1, %2, %0;" : "+l"(acc) : "l"(a), "l"(b));
}
__device__ __forceinline__ void unpk2(unsigned long long v, float& lo, float& hi) {
    unsigned int l, h;
    asm("mov.b64 {%0, %1}, %2;" : "=r"(l), "=r"(h) : "l"(v));
    lo = __uint_as_float(l);
    hi = __uint_as_float(h);
}
__device__ __forceinline__ void cp16(void* dst, const void* src) {
    unsigned s = (unsigned)__cvta_generic_to_shared(dst);
    asm volatile("cp.async.cg.shared.global [%0], [%1], 16;" :: "r"(s), "l"(src) : "memory");
}
#define CP_COMMIT() asm volatile("cp.async.commit_group;" ::: "memory")
#define CP_WAIT1()  asm volatile("cp.async.wait_group 1;" ::: "memory")
#define CP_WAIT0()  asm volatile("cp.async.wait_group 0;" ::: "memory")

// ---------------- kernel: duplicate h into d-major (a,a) pairs ----------------
__global__ __launch_bounds__(256)
void adup_kernel(const float* __restrict__ h_top, const float* __restrict__ h_bot) {
    int lvl = blockIdx.y;
    const float* h = lvl ? h_bot : h_top;
    size_t idx = (size_t)blockIdx.x * 256 + threadIdx.x;   // float4 index
    float4 v = ((const float4*)h)[idx];
    size_t e = idx * 4;                                    // element index: b*DIM*TLEN + d*TLEN + t
    int t = (int)(e & (TLEN - 1));
    int d = (int)((e >> 11) & (DIM - 1));
    int b = (int)(e >> 19);
    float2* dst = g_adup + ((size_t)lvl * DIM + d) * NPTS + b * TLEN + t;
    dst[0] = make_float2(v.x, v.x);
    dst[1] = make_float2(v.y, v.y);
    dst[2] = make_float2(v.z, v.z);
    dst[3] = make_float2(v.w, v.w);
}

// ---------------- kernel: transpose codebook to [d][c] ----------------
__global__ __launch_bounds__(256)
void btrans_kernel(const float* __restrict__ cb_top, const float* __restrict__ cb_bot) {
    __shared__ float s[32][33];
    int lvl = blockIdx.z;
    const float* cb = lvl ? cb_bot : cb_top;
    int c0 = blockIdx.x * 32, d0 = blockIdx.y * 32;
    int lx = threadIdx.x & 31, ly = threadIdx.x >> 5;   // ly 0..7
#pragma unroll
    for (int k = 0; k < 4; k++)
        s[ly + 8 * k][lx] = cb[(size_t)(c0 + ly + 8 * k) * DIM + d0 + lx];
    __syncthreads();
#pragma unroll
    for (int k = 0; k < 4; k++)
        g_bt[((size_t)lvl * DIM + d0 + ly + 8 * k) * KCODES + c0 + lx] = s[lx][ly + 8 * k];
}

// ---------------- kernel: codebook norms -> packed -cn/2 + counter reset ----------------
__global__ __launch_bounds__(256)
void cnorm_kernel(const float* __restrict__ cb_top, const float* __restrict__ cb_bot) {
    __shared__ float s8[8];
    int lvl = blockIdx.y;
    if (blockIdx.x == 0 && threadIdx.x == 0) g_refine_count[lvl] = 0;
    const float* cb = lvl ? cb_bot : cb_top;
    int w = threadIdx.x >> 5, lane = threadIdx.x & 31;
    int c = blockIdx.x * 8 + w;
    const float* row = cb + (size_t)c * DIM;
    float sacc = 0.f;
#pragma unroll
    for (int i = 0; i < DIM / 32; i++) {
        float v = row[i * 32 + lane];
        sacc = fmaf(v, v, sacc);
    }
#pragma unroll
    for (int o = 16; o; o >>= 1) sacc += __shfl_down_sync(0xffffffffu, sacc, o);
    if (lane == 0) s8[w] = sacc;
    __syncthreads();
    if (threadIdx.x < 4)
        g_cninit[lvl * (KCODES / 2) + blockIdx.x * 4 + threadIdx.x] =
            make_float2(-0.5f * s8[2 * threadIdx.x], -0.5f * s8[2 * threadIdx.x + 1]);
}

// ---------------- argmin GEMM (packed f32x2, cp.async pipeline) ----------------
__device__ __forceinline__ void issue_stage(
    float2 (*AB)[16][128], float (*BB)[16][128],
    const float2* __restrict__ adup, const float* __restrict__ bt,
    int m0, int s, int tid) {
    int ct = s >> 4, dss = s & 15, buf = s & 1;
    int d0 = dss * 16, c0 = ct * 128;
#pragma unroll
    for (int k = 0; k < 4; k++) {                       // A: 16KB = 1024 x 16B
        int q = tid + k * 256;
        int row = q >> 6, col = q & 63;
        cp16(&AB[buf][row][col * 2],
             adup + (size_t)(d0 + row) * NPTS + m0 + col * 2);
    }
#pragma unroll
    for (int k = 0; k < 2; k++) {                       // B: 8KB = 512 x 16B
        int q = tid + k * 256;
        int row = q >> 5, col = q & 31;
        cp16(&BB[buf][row][col * 4],
             bt + (size_t)(d0 + row) * KCODES + c0 + col * 4);
    }
    CP_COMMIT();
}

__global__ __launch_bounds__(256, 2)
void argmin_kernel() {
    __shared__ float2 AB[2][16][128];   // 32KB: [buf][dd][point dup pair]
    __shared__ float  BB[2][16][128];   // 16KB: [buf][dd][code]

    int tid = threadIdx.x, lvl = blockIdx.y;
    int m0 = blockIdx.x * 128;
    int ty = tid >> 4, tx = tid & 15;
    const float2* adup = g_adup + (size_t)lvl * DIM * NPTS;
    const float*  bt   = g_bt   + (size_t)lvl * DIM * KCODES;

    float best[8], b2[8];
    int   bidx[8];
#pragma unroll
    for (int i = 0; i < 8; i++) { best[i] = -FLT_MAX; b2[i] = -FLT_MAX; bidx[i] = 0; }

    issue_stage(AB, BB, adup, bt, m0, 0, tid);

    unsigned long long acc[8][4];

#pragma unroll 1
    for (int ct = 0; ct < 8; ct++) {
        // init acc with packed -cn/2 (folds the |e|^2 term; epilogue becomes compare-only)
        const float2* cip = g_cninit + lvl * (KCODES / 2) + ((ct * 128 + tx * 8) >> 1);
        ulonglong2 ci01 = *(const ulonglong2*)cip;
        ulonglong2 ci23 = *(const ulonglong2*)(cip + 2);
#pragma unroll
        for (int i = 0; i < 8; i++) {
            acc[i][0] = ci01.x; acc[i][1] = ci01.y;
            acc[i][2] = ci23.x; acc[i][3] = ci23.y;
        }

#pragma unroll 1
        for (int dss = 0; dss < 16; dss++) {
            int s = ct * 16 + dss, buf = s & 1;
            if (s < 127) { issue_stage(AB, BB, adup, bt, m0, s + 1, tid); CP_WAIT1(); }
            else         { CP_WAIT0(); }
            __syncthreads();

#pragma unroll
            for (int dd = 0; dd < 16; dd++) {
                ulonglong2 a01 = *(const ulonglong2*)&AB[buf][dd][ty * 8];
                ulonglong2 a23 = *(const ulonglong2*)&AB[buf][dd][ty * 8 + 2];
                ulonglong2 a45 = *(const ulonglong2*)&AB[buf][dd][ty * 8 + 4];
                ulonglong2 a67 = *(const ulonglong2*)&AB[buf][dd][ty * 8 + 6];
                ulonglong2 b03 = *(const ulonglong2*)&BB[buf][dd][tx * 8];
                ulonglong2 b47 = *(const ulonglong2*)&BB[buf][dd][tx * 8 + 4];
                unsigned long long A8[8] = {a01.x, a01.y, a23.x, a23.y,
                                            a45.x, a45.y, a67.x, a67.y};
#pragma unroll
                for (int i = 0; i < 8; i++) {
                    fma2(acc[i][0], A8[i], b03.x);
                    fma2(acc[i][1], A8[i], b03.y);
                    fma2(acc[i][2], A8[i], b47.x);
                    fma2(acc[i][3], A8[i], b47.y);
                }
            }
            __syncthreads();
        }

        // fold this code-tile into running top-2 (maximize s'); ascending c order
#pragma unroll
        for (int j = 0; j < 4; j++) {
            int ce = ct * 128 + tx * 8 + 2 * j;
#pragma unroll
            for (int i = 0; i < 8; i++) {
                float se, so;
                unpk2(acc[i][j], se, so);
                if (se > best[i]) { b2[i] = best[i]; best[i] = se; bidx[i] = ce; }
                else if (se > b2[i]) b2[i] = se;
                if (so > best[i]) { b2[i] = best[i]; best[i] = so; bidx[i] = ce + 1; }
                else if (so > b2[i]) b2[i] = so;
            }
        }
    }

    // cross-thread merge over the 16 tx columns per point
    __syncthreads();
    float* sval = (float*)AB;                 // 16*128 floats (8KB)
    int*   sidx = (int*)(sval + 2048);        // 16*128 ints  (8KB) -- still inside AB (32KB)
    float* s2v  = (float*)BB;                 // 16*128 floats (8KB) inside BB
#pragma unroll
    for (int i = 0; i < 8; i++) {
        int p = ty * 8 + i;
        sval[tx * 128 + p] = best[i];
        sidx[tx * 128 + p] = bidx[i];
        s2v[tx * 128 + p]  = b2[i];
    }
    __syncthreads();
    if (tid < 128) {
        float bv = sval[tid];
        int   bi = sidx[tid];
        float bs = s2v[tid];
#pragma unroll
        for (int x = 1; x < 16; x++) {
            float v  = sval[x * 128 + tid];
            int   ii = sidx[x * 128 + tid];
            float v2 = s2v[x * 128 + tid];
            if (v > bv || (v == bv && ii < bi)) { bs = fmaxf(bv, v2); bv = v; bi = ii; }
            else                                 bs = fmaxf(bs, v);
        }
        g_idx[lvl][m0 + tid] = bi;
        if (bv - bs < TAU_S) {
            int pos = atomicAdd(&g_refine_count[lvl], 1);
            g_refine_list[lvl][pos] = m0 + tid;
        }
    }
}

// ---------------- kernel: f64 exact refinement of near-ties ----------------
__global__ __launch_bounds__(256)
void refine_kernel(const float* __restrict__ h_top, const float* __restrict__ h_bot,
                   const float* __restrict__ cb_top, const float* __restrict__ cb_bot) {
    int lvl = blockIdx.y;
    const float* h  = lvl ? h_bot  : h_top;
    const float* cb = lvl ? cb_bot : cb_top;
    int cnt = g_refine_count[lvl];

    __shared__ double xs[DIM];
    __shared__ double rv[8];
    __shared__ int    ri[8];

    int tid = threadIdx.x;
    int w = tid >> 5, lane = tid & 31;

    for (int e = blockIdx.x; e < cnt; e += gridDim.x) {
        int p = g_refine_list[lvl][e];
        int b = p / TLEN, t = p % TLEN;
        __syncthreads();
        if (tid < DIM)
            xs[tid] = (double)h[((size_t)b * DIM + tid) * TLEN + t];
        __syncthreads();

        double bv = 1e300;
        int    bi = 0;
        for (int k = 0; k < KCODES / 8; k++) {
            int c = w * (KCODES / 8) + k;
            const float* row = cb + (size_t)c * DIM;
            double s = 0.0;
#pragma unroll
            for (int i = 0; i < DIM / 32; i++) {
                int d = i * 32 + lane;
                double diff = xs[d] - (double)row[d];
                s = fma(diff, diff, s);
            }
#pragma unroll
            for (int o = 16; o; o >>= 1) s += __shfl_down_sync(0xffffffffu, s, o);
            s = __shfl_sync(0xffffffffu, s, 0);
            if (s < bv) { bv = s; bi = c; }
        }
        if (lane == 0) { rv[w] = bv; ri[w] = bi; }
        __syncthreads();
        if (tid == 0) {
            double fbv = rv[0]; int fbi = ri[0];
#pragma unroll
            for (int x = 1; x < 8; x++)
                if (rv[x] < fbv || (rv[x] == fbv && ri[x] < fbi)) { fbv = rv[x]; fbi = ri[x]; }
            g_idx[lvl][p] = fbi;
        }
    }
}

// ---------------- kernel: gather z_q + per-block loss partials ----------------
__global__ __launch_bounds__(256)
void gather_kernel(const float* __restrict__ h_top, const float* __restrict__ h_bot,
                   const float* __restrict__ cb_top, const float* __restrict__ cb_bot,
                   float* __restrict__ out) {
    int lvl = blockIdx.z;
    const float* h  = lvl ? h_bot  : h_top;
    const float* cb = lvl ? cb_bot : cb_top;
    float* z = out + (size_t)lvl * NELEM;

    int b = blockIdx.y;
    int t0 = blockIdx.x * 32;
    int tid = threadIdx.x;

    __shared__ int   sidx[32];
    __shared__ float sh[32 * 33];
    __shared__ float red[256];

    if (tid < 32) sidx[tid] = g_idx[lvl][b * TLEN + t0 + tid];
    __syncthreads();

    float lacc = 0.f;
    int j2 = tid >> 3, l8 = tid & 7;

    for (int dc = 0; dc < DIM; dc += 32) {
        float4 v = *(const float4*)(cb + (size_t)sidx[j2] * DIM + dc + l8 * 4);
        sh[(l8 * 4 + 0) * 33 + j2] = v.x;
        sh[(l8 * 4 + 1) * 33 + j2] = v.y;
        sh[(l8 * 4 + 2) * 33 + j2] = v.z;
        sh[(l8 * 4 + 3) * 33 + j2] = v.w;
        __syncthreads();
#pragma unroll
        for (int it = 0; it < 4; it++) {
            int i = tid + it * 256;
            int dl = i >> 5, j = i & 31;
            size_t off = ((size_t)b * DIM + dc + dl) * TLEN + t0 + j;
            float zz = sh[dl * 33 + j];
            z[off] = zz;
            float e = h[off] - zz;
            lacc = fmaf(e, e, lacc);
        }
        __syncthreads();
    }

    red[tid] = lacc;
    __syncthreads();
#pragma unroll
    for (int s = 128; s; s >>= 1) {
        if (tid < s) red[tid] += red[tid + s];
        __syncthreads();
    }
    if (tid == 0) g_partial[lvl][blockIdx.y * (TLEN / 32) + blockIdx.x] = red[0];
}

// ---------------- kernel: finalize scalars ----------------
__global__ __launch_bounds__(1024)
void finalize_kernel(float* __restrict__ out) {
    __shared__ int   hist[KCODES];
    __shared__ float red[1024];
    int tid = threadIdx.x;

    float sums[2];
#pragma unroll
    for (int lvl = 0; lvl < 2; lvl++) {
        red[tid] = g_partial[lvl][tid];
        __syncthreads();
        for (int s = 512; s; s >>= 1) {
            if (tid < s) red[tid] += red[tid + s];
            __syncthreads();
        }
        sums[lvl] = red[0];
        __syncthreads();
    }
    float loss = sums[0] * (1.f / (float)NELEM) + sums[1] * (1.f / (float)NELEM);

    float ppl[2];
#pragma unroll
    for (int lvl = 0; lvl < 2; lvl++) {
        hist[tid] = 0;
        __syncthreads();
#pragma unroll
        for (int i = 0; i < NPTS / 1024; i++)
            atomicAdd(&hist[g_idx[lvl][i * 1024 + tid]], 1);
        __syncthreads();
        float p = (float)hist[tid] * (1.f / (float)NPTS);
        red[tid] = p * logf(p + 1e-10f);
        __syncthreads();
        for (int s = 512; s; s >>= 1) {
            if (tid < s) red[tid] += red[tid + s];
            __syncthreads();
        }
        ppl[lvl] = expf(-red[0]);
        __syncthreads();
    }

    if (tid == 0) {
        size_t base = (size_t)2 * NELEM;
        out[base + 0] = loss;
        out[base + 1] = loss;
        out[base + 2] = ppl[0];
        out[base + 3] = ppl[1];
    }
}

// ---------------- launcher ----------------
extern "C" void kernel_launch(void* const* d_in, const int* in_sizes, int n_in,
                              void* d_out, int out_size) {
    const float* h_top  = (const float*)d_in[0];
    const float* h_bot  = (const float*)d_in[1];
    const float* cb_top = (const float*)d_in[2];
    const float* cb_bot = (const float*)d_in[3];
    float* out = (float*)d_out;

    adup_kernel  <<<dim3(NELEM / 1024, LEVELS), 256>>>(h_top, h_bot);
    btrans_kernel<<<dim3(KCODES / 32, DIM / 32, LEVELS), 256>>>(cb_top, cb_bot);
    cnorm_kernel <<<dim3(KCODES / 8, LEVELS), 256>>>(cb_top, cb_bot);
    argmin_kernel<<<dim3(NPTS / 128, LEVELS), 256>>>();
    refine_kernel<<<dim3(256, LEVELS), 256>>>(h_top, h_bot, cb_top, cb_bot);
    gather_kernel<<<dim3(TLEN / 32, BATCH, LEVELS), 256>>>(h_top, h_bot, cb_top, cb_bot, out);
    finalize_kernel<<<1, 1024>>>(out);
}

// round 5
// speedup vs baseline: 1.0838x; 1.0838x over previous
#include <cuda_runtime.h>
#include <cstdint>
#include <cfloat>

#define LEVELS 2
#define BATCH  16
#define DIM    256
#define TLEN   2048
#define NPTS   (BATCH * TLEN)       // 32768 points per level
#define KCODES 1024
#define NELEM  (BATCH * DIM * TLEN) // 8388608 per level
#define GATHER_BLOCKS (BATCH * (TLEN / 32))
#define TAU_S  0.01f                // s-space gap == 0.02 distance gap (R2-validated)

// ---------------- scratch (no allocations allowed) ----------------
__device__ float  g_bt[(size_t)LEVELS * DIM * KCODES];     // codebook transposed: [lvl][d][c]
__device__ float2 g_cninit[LEVELS * (KCODES / 2)];         // packed (-cn/2) pairs
__device__ float  g_partial[LEVELS][GATHER_BLOCKS];
__device__ int    g_idx[LEVELS][NPTS];
__device__ int    g_refine_count[LEVELS];
__device__ int    g_refine_list[LEVELS][NPTS];

// ---------------- f32x2 / async helpers ----------------
__device__ __forceinline__ unsigned long long pk2(float a) {
    unsigned long long r;
    unsigned int u = __float_as_uint(a);
    asm("mov.b64 %0, {%1, %1};" : "=l"(r) : "r"(u));
    return r;
}
__device__ __forceinline__ void fma2(unsigned long long& acc,
                                     unsigned long long a,
                                     unsigned long long b) {
    asm("fma.rn.f32x2 %0, %1, %2, %0;" : "+l"(acc) : "l"(a), "l"(b));
}
__device__ __forceinline__ void unpk2(unsigned long long v, float& lo, float& hi) {
    unsigned int l, h;
    asm("mov.b64 {%0, %1}, %2;" : "=r"(l), "=r"(h) : "l"(v));
    lo = __uint_as_float(l);
    hi = __uint_as_float(h);
}
__device__ __forceinline__ void cp16(void* dst, const void* src) {
    unsigned s = (unsigned)__cvta_generic_to_shared(dst);
    asm volatile("cp.async.cg.shared.global [%0], [%1], 16;" :: "r"(s), "l"(src) : "memory");
}
#define CP_COMMIT() asm volatile("cp.async.commit_group;" ::: "memory")
#define CP_WAIT1()  asm volatile("cp.async.wait_group 1;" ::: "memory")
#define CP_WAIT0()  asm volatile("cp.async.wait_group 0;" ::: "memory")

// ---------------- kernel: transpose codebook to [d][c] ----------------
__global__ __launch_bounds__(256)
void btrans_kernel(const float* __restrict__ cb_top, const float* __restrict__ cb_bot) {
    __shared__ float s[32][33];
    int lvl = blockIdx.z;
    const float* cb = lvl ? cb_bot : cb_top;
    int c0 = blockIdx.x * 32, d0 = blockIdx.y * 32;
    int lx = threadIdx.x & 31, ly = threadIdx.x >> 5;   // ly 0..7
#pragma unroll
    for (int k = 0; k < 4; k++)
        s[ly + 8 * k][lx] = cb[(size_t)(c0 + ly + 8 * k) * DIM + d0 + lx];
    __syncthreads();
#pragma unroll
    for (int k = 0; k < 4; k++)
        g_bt[((size_t)lvl * DIM + d0 + ly + 8 * k) * KCODES + c0 + lx] = s[lx][ly + 8 * k];
}

// ---------------- kernel: codebook norms -> packed -cn/2 + counter reset ----------------
__global__ __launch_bounds__(256)
void cnorm_kernel(const float* __restrict__ cb_top, const float* __restrict__ cb_bot) {
    __shared__ float s8[8];
    int lvl = blockIdx.y;
    if (blockIdx.x == 0 && threadIdx.x == 0) g_refine_count[lvl] = 0;
    const float* cb = lvl ? cb_bot : cb_top;
    int w = threadIdx.x >> 5, lane = threadIdx.x & 31;
    int c = blockIdx.x * 8 + w;
    const float* row = cb + (size_t)c * DIM;
    float sacc = 0.f;
#pragma unroll
    for (int i = 0; i < DIM / 32; i++) {
        float v = row[i * 32 + lane];
        sacc = fmaf(v, v, sacc);
    }
#pragma unroll
    for (int o = 16; o; o >>= 1) sacc += __shfl_down_sync(0xffffffffu, sacc, o);
    if (lane == 0) s8[w] = sacc;
    __syncthreads();
    if (threadIdx.x < 4)
        g_cninit[lvl * (KCODES / 2) + blockIdx.x * 4 + threadIdx.x] =
            make_float2(-0.5f * s8[2 * threadIdx.x], -0.5f * s8[2 * threadIdx.x + 1]);
}

// ---------------- argmin GEMM (packed f32x2, cp.async pipeline, A direct from h) ----------------
// A tile: 16 dds x 128 consecutive t of one b -> contiguous 512B rows in h. No transpose needed.
__device__ __forceinline__ void issue_stage(
    float (*AS)[16][128], float (*BS)[16][128],
    const float* __restrict__ hbase, const float* __restrict__ bt,
    int s, int tid) {
    int ct = s >> 4, dss = s & 15, buf = s & 1;
    int d0 = dss * 16, c0 = ct * 128;
    int row = tid >> 5, col = tid & 31;         // 512 cp16 ops, 2 per thread
#pragma unroll
    for (int k = 0; k < 2; k++) {
        int r = row + k * 8;
        cp16(&AS[buf][r][col * 4], hbase + (size_t)(d0 + r) * TLEN + col * 4);
        cp16(&BS[buf][r][col * 4], bt + (size_t)(d0 + r) * KCODES + c0 + col * 4);
    }
    CP_COMMIT();
}

__global__ __launch_bounds__(256, 2)
void argmin_kernel(const float* __restrict__ h_top, const float* __restrict__ h_bot) {
    __shared__ float AS[2][16][128];   // 16KB: [buf][dd][t]     (undup A)
    __shared__ float BS[2][16][128];   // 16KB: [buf][dd][code]

    int tid = threadIdx.x, lvl = blockIdx.y;
    int m0 = blockIdx.x * 128;
    int b  = m0 / TLEN, t0 = m0 % TLEN;
    int ty = tid >> 4, tx = tid & 15;
    const float* h  = lvl ? h_bot : h_top;
    const float* hbase = h + (size_t)b * DIM * TLEN + t0;
    const float* bt = g_bt + (size_t)lvl * DIM * KCODES;

    float best[8], b2[8];
    int   bidx[8];
#pragma unroll
    for (int i = 0; i < 8; i++) { best[i] = -FLT_MAX; b2[i] = -FLT_MAX; bidx[i] = 0; }

    issue_stage(AS, BS, hbase, bt, 0, tid);

    unsigned long long acc[8][4];

#pragma unroll 1
    for (int ct = 0; ct < 8; ct++) {
        // init acc with packed -cn/2 (folds |e|^2; epilogue is compare-only)
        const float2* cip = g_cninit + lvl * (KCODES / 2) + ((ct * 128 + tx * 8) >> 1);
        ulonglong2 ci01 = *(const ulonglong2*)cip;
        ulonglong2 ci23 = *(const ulonglong2*)(cip + 2);
#pragma unroll
        for (int i = 0; i < 8; i++) {
            acc[i][0] = ci01.x; acc[i][1] = ci01.y;
            acc[i][2] = ci23.x; acc[i][3] = ci23.y;
        }

#pragma unroll 1
        for (int dss = 0; dss < 16; dss++) {
            int s = ct * 16 + dss, buf = s & 1;
            if (s < 127) { issue_stage(AS, BS, hbase, bt, s + 1, tid); CP_WAIT1(); }
            else         { CP_WAIT0(); }
            __syncthreads();

#pragma unroll
            for (int dd = 0; dd < 16; dd++) {
                float4 a03 = *(const float4*)&AS[buf][dd][ty * 8];
                float4 a47 = *(const float4*)&AS[buf][dd][ty * 8 + 4];
                ulonglong2 b03 = *(const ulonglong2*)&BS[buf][dd][tx * 8];
                ulonglong2 b47 = *(const ulonglong2*)&BS[buf][dd][tx * 8 + 4];
                unsigned long long A8[8] = {
                    pk2(a03.x), pk2(a03.y), pk2(a03.z), pk2(a03.w),
                    pk2(a47.x), pk2(a47.y), pk2(a47.z), pk2(a47.w)};
#pragma unroll
                for (int i = 0; i < 8; i++) {
                    fma2(acc[i][0], A8[i], b03.x);
                    fma2(acc[i][1], A8[i], b03.y);
                    fma2(acc[i][2], A8[i], b47.x);
                    fma2(acc[i][3], A8[i], b47.y);
                }
            }
            __syncthreads();
        }

        // fold this code-tile into running top-2 (maximize s'); ascending c order
#pragma unroll
        for (int j = 0; j < 4; j++) {
            int ce = ct * 128 + tx * 8 + 2 * j;
#pragma unroll
            for (int i = 0; i < 8; i++) {
                float se, so;
                unpk2(acc[i][j], se, so);
                if (se > best[i]) { b2[i] = best[i]; best[i] = se; bidx[i] = ce; }
                else if (se > b2[i]) b2[i] = se;
                if (so > best[i]) { b2[i] = best[i]; best[i] = so; bidx[i] = ce + 1; }
                else if (so > b2[i]) b2[i] = so;
            }
        }
    }

    // cross-thread merge over the 16 tx columns per point
    __syncthreads();
    float* sval = (float*)AS;                 // 2048 floats (8KB) within AS (16KB)
    int*   sidx = (int*)(sval + 2048);        // 2048 ints   (8KB) within AS
    float* s2v  = (float*)BS;                 // 2048 floats (8KB) within BS
#pragma unroll
    for (int i = 0; i < 8; i++) {
        int p = ty * 8 + i;
        sval[tx * 128 + p] = best[i];
        sidx[tx * 128 + p] = bidx[i];
        s2v[tx * 128 + p]  = b2[i];
    }
    __syncthreads();
    if (tid < 128) {
        float bv = sval[tid];
        int   bi = sidx[tid];
        float bs = s2v[tid];
#pragma unroll
        for (int x = 1; x < 16; x++) {
            float v  = sval[x * 128 + tid];
            int   ii = sidx[x * 128 + tid];
            float v2 = s2v[x * 128 + tid];
            if (v > bv || (v == bv && ii < bi)) { bs = fmaxf(bv, v2); bv = v; bi = ii; }
            else                                 bs = fmaxf(bs, v);
        }
        g_idx[lvl][m0 + tid] = bi;
        if (bv - bs < TAU_S) {
            int pos = atomicAdd(&g_refine_count[lvl], 1);
            g_refine_list[lvl][pos] = m0 + tid;
        }
    }
}

// ---------------- kernel: f64 exact refinement of near-ties ----------------
__global__ __launch_bounds__(256)
void refine_kernel(const float* __restrict__ h_top, const float* __restrict__ h_bot,
                   const float* __restrict__ cb_top, const float* __restrict__ cb_bot) {
    int lvl = blockIdx.y;
    const float* h  = lvl ? h_bot  : h_top;
    const float* cb = lvl ? cb_bot : cb_top;
    int cnt = g_refine_count[lvl];

    __shared__ double xs[DIM];
    __shared__ double rv[8];
    __shared__ int    ri[8];

    int tid = threadIdx.x;
    int w = tid >> 5, lane = tid & 31;

    for (int e = blockIdx.x; e < cnt; e += gridDim.x) {
        int p = g_refine_list[lvl][e];
        int b = p / TLEN, t = p % TLEN;
        __syncthreads();
        if (tid < DIM)
            xs[tid] = (double)h[((size_t)b * DIM + tid) * TLEN + t];
        __syncthreads();

        double bv = 1e300;
        int    bi = 0;
        for (int k = 0; k < KCODES / 8; k++) {
            int c = w * (KCODES / 8) + k;
            const float* row = cb + (size_t)c * DIM;
            double s = 0.0;
#pragma unroll
            for (int i = 0; i < DIM / 32; i++) {
                int d = i * 32 + lane;
                double diff = xs[d] - (double)row[d];
                s = fma(diff, diff, s);
            }
#pragma unroll
            for (int o = 16; o; o >>= 1) s += __shfl_down_sync(0xffffffffu, s, o);
            s = __shfl_sync(0xffffffffu, s, 0);
            if (s < bv) { bv = s; bi = c; }
        }
        if (lane == 0) { rv[w] = bv; ri[w] = bi; }
        __syncthreads();
        if (tid == 0) {
            double fbv = rv[0]; int fbi = ri[0];
#pragma unroll
            for (int x = 1; x < 8; x++)
                if (rv[x] < fbv || (rv[x] == fbv && ri[x] < fbi)) { fbv = rv[x]; fbi = ri[x]; }
            g_idx[lvl][p] = fbi;
        }
    }
}

// ---------------- kernel: gather z_q + per-block loss partials ----------------
__global__ __launch_bounds__(256)
void gather_kernel(const float* __restrict__ h_top, const float* __restrict__ h_bot,
                   const float* __restrict__ cb_top, const float* __restrict__ cb_bot,
                   float* __restrict__ out) {
    int lvl = blockIdx.z;
    const float* h  = lvl ? h_bot  : h_top;
    const float* cb = lvl ? cb_bot : cb_top;
    float* z = out + (size_t)lvl * NELEM;

    int b = blockIdx.y;
    int t0 = blockIdx.x * 32;
    int tid = threadIdx.x;

    __shared__ int   sidx[32];
    __shared__ float sh[32 * 33];
    __shared__ float red[256];

    if (tid < 32) sidx[tid] = g_idx[lvl][b * TLEN + t0 + tid];
    __syncthreads();

    float lacc = 0.f;
    int j2 = tid >> 3, l8 = tid & 7;

    for (int dc = 0; dc < DIM; dc += 32) {
        float4 v = *(const float4*)(cb + (size_t)sidx[j2] * DIM + dc + l8 * 4);
        sh[(l8 * 4 + 0) * 33 + j2] = v.x;
        sh[(l8 * 4 + 1) * 33 + j2] = v.y;
        sh[(l8 * 4 + 2) * 33 + j2] = v.z;
        sh[(l8 * 4 + 3) * 33 + j2] = v.w;
        __syncthreads();
#pragma unroll
        for (int it = 0; it < 4; it++) {
            int i = tid + it * 256;
            int dl = i >> 5, j = i & 31;
            size_t off = ((size_t)b * DIM + dc + dl) * TLEN + t0 + j;
            float zz = sh[dl * 33 + j];
            z[off] = zz;
            float e = h[off] - zz;
            lacc = fmaf(e, e, lacc);
        }
        __syncthreads();
    }

    red[tid] = lacc;
    __syncthreads();
#pragma unroll
    for (int s = 128; s; s >>= 1) {
        if (tid < s) red[tid] += red[tid + s];
        __syncthreads();
    }
    if (tid == 0) g_partial[lvl][blockIdx.y * (TLEN / 32) + blockIdx.x] = red[0];
}

// ---------------- kernel: finalize scalars ----------------
__global__ __launch_bounds__(1024)
void finalize_kernel(float* __restrict__ out) {
    __shared__ int   hist[KCODES];
    __shared__ float red[1024];
    int tid = threadIdx.x;

    float sums[2];
#pragma unroll
    for (int lvl = 0; lvl < 2; lvl++) {
        red[tid] = g_partial[lvl][tid];
        __syncthreads();
        for (int s = 512; s; s >>= 1) {
            if (tid < s) red[tid] += red[tid + s];
            __syncthreads();
        }
        sums[lvl] = red[0];
        __syncthreads();
    }
    float loss = sums[0] * (1.f / (float)NELEM) + sums[1] * (1.f / (float)NELEM);

    float ppl[2];
#pragma unroll
    for (int lvl = 0; lvl < 2; lvl++) {
        hist[tid] = 0;
        __syncthreads();
#pragma unroll
        for (int i = 0; i < NPTS / 1024; i++)
            atomicAdd(&hist[g_idx[lvl][i * 1024 + tid]], 1);
        __syncthreads();
        float p = (float)hist[tid] * (1.f / (float)NPTS);
        red[tid] = p * logf(p + 1e-10f);
        __syncthreads();
        for (int s = 512; s; s >>= 1) {
            if (tid < s) red[tid] += red[tid + s];
            __syncthreads();
        }
        ppl[lvl] = expf(-red[0]);
        __syncthreads();
    }

    if (tid == 0) {
        size_t base = (size_t)2 * NELEM;
        out[base + 0] = loss;
        out[base + 1] = loss;
        out[base + 2] = ppl[0];
        out[base + 3] = ppl[1];
    }
}

// ---------------- launcher ----------------
extern "C" void kernel_launch(void* const* d_in, const int* in_sizes, int n_in,
                              void* d_out, int out_size) {
    const float* h_top  = (const float*)d_in[0];
    const float* h_bot  = (const float*)d_in[1];
    const float* cb_top = (const float*)d_in[2];
    const float* cb_bot = (const float*)d_in[3];
    float* out = (float*)d_out;

    btrans_kernel<<<dim3(KCODES / 32, DIM / 32, LEVELS), 256>>>(cb_top, cb_bot);
    cnorm_kernel <<<dim3(KCODES / 8, LEVELS), 256>>>(cb_top, cb_bot);
    argmin_kernel<<<dim3(NPTS / 128, LEVELS), 256>>>(h_top, h_bot);
    refine_kernel<<<dim3(256, LEVELS), 256>>>(h_top, h_bot, cb_top, cb_bot);
    gather_kernel<<<dim3(TLEN / 32, BATCH, LEVELS), 256>>>(h_top, h_bot, cb_top, cb_bot, out);
    finalize_kernel<<<1, 1024>>>(out);
}

// round 6
// speedup vs baseline: 1.7925x; 1.6540x over previous
#include <cuda_runtime.h>
#include <cstdint>
#include <cfloat>

#define LEVELS 2
#define BATCH  16
#define DIM    256
#define TLEN   2048
#define NPTS   (BATCH * TLEN)       // 32768 points per level
#define KCODES 1024
#define NELEM  (BATCH * DIM * TLEN) // 8388608 per level
#define GATHER_BLOCKS (BATCH * (TLEN / 32))
#define TAU_S  0.01f                // s-space gap == 0.02 distance gap (R2-validated)

// ---------------- scratch (no allocations allowed) ----------------
__device__ float  g_bt[(size_t)LEVELS * DIM * KCODES];     // codebook transposed: [lvl][d][c]
__device__ float2 g_cninit[LEVELS * (KCODES / 2)];         // packed (-cn/2) pairs
__device__ float  g_partial[LEVELS][GATHER_BLOCKS];
__device__ int    g_idx[LEVELS][NPTS];
__device__ int    g_refine_count[LEVELS];
__device__ int    g_refine_list[LEVELS][NPTS];

// ---------------- f32x2 / async helpers ----------------
__device__ __forceinline__ unsigned long long pk2(float a) {
    unsigned long long r;
    unsigned int u = __float_as_uint(a);
    asm("mov.b64 %0, {%1, %1};" : "=l"(r) : "r"(u));
    return r;
}
__device__ __forceinline__ void fma2(unsigned long long& acc,
                                     unsigned long long a,
                                     unsigned long long b) {
    asm("fma.rn.f32x2 %0, %1, %2, %0;" : "+l"(acc) : "l"(a), "l"(b));
}
__device__ __forceinline__ void unpk2(unsigned long long v, float& lo, float& hi) {
    unsigned int l, h;
    asm("mov.b64 {%0, %1}, %2;" : "=r"(l), "=r"(h) : "l"(v));
    lo = __uint_as_float(l);
    hi = __uint_as_float(h);
}
__device__ __forceinline__ void cp16(void* dst, const void* src) {
    unsigned s = (unsigned)__cvta_generic_to_shared(dst);
    asm volatile("cp.async.cg.shared.global [%0], [%1], 16;" :: "r"(s), "l"(src) : "memory");
}
#define CP_COMMIT() asm volatile("cp.async.commit_group;" ::: "memory")
#define CP_WAIT1()  asm volatile("cp.async.wait_group 1;" ::: "memory")
#define CP_WAIT0()  asm volatile("cp.async.wait_group 0;" ::: "memory")

// ---------------- kernel: transpose codebook to [d][c] ----------------
__global__ __launch_bounds__(256)
void btrans_kernel(const float* __restrict__ cb_top, const float* __restrict__ cb_bot) {
    __shared__ float s[32][33];
    int lvl = blockIdx.z;
    const float* cb = lvl ? cb_bot : cb_top;
    int c0 = blockIdx.x * 32, d0 = blockIdx.y * 32;
    int lx = threadIdx.x & 31, ly = threadIdx.x >> 5;   // ly 0..7
#pragma unroll
    for (int k = 0; k < 4; k++)
        s[ly + 8 * k][lx] = cb[(size_t)(c0 + ly + 8 * k) * DIM + d0 + lx];
    __syncthreads();
#pragma unroll
    for (int k = 0; k < 4; k++)
        g_bt[((size_t)lvl * DIM + d0 + ly + 8 * k) * KCODES + c0 + lx] = s[lx][ly + 8 * k];
}

// ---------------- kernel: codebook norms -> packed -cn/2 + counter reset ----------------
__global__ __launch_bounds__(256)
void cnorm_kernel(const float* __restrict__ cb_top, const float* __restrict__ cb_bot) {
    __shared__ float s8[8];
    int lvl = blockIdx.y;
    if (blockIdx.x == 0 && threadIdx.x == 0) g_refine_count[lvl] = 0;
    const float* cb = lvl ? cb_bot : cb_top;
    int w = threadIdx.x >> 5, lane = threadIdx.x & 31;
    int c = blockIdx.x * 8 + w;
    const float* row = cb + (size_t)c * DIM;
    float sacc = 0.f;
#pragma unroll
    for (int i = 0; i < DIM / 32; i++) {
        float v = row[i * 32 + lane];
        sacc = fmaf(v, v, sacc);
    }
#pragma unroll
    for (int o = 16; o; o >>= 1) sacc += __shfl_down_sync(0xffffffffu, sacc, o);
    if (lane == 0) s8[w] = sacc;
    __syncthreads();
    if (threadIdx.x < 4)
        g_cninit[lvl * (KCODES / 2) + blockIdx.x * 4 + threadIdx.x] =
            make_float2(-0.5f * s8[2 * threadIdx.x], -0.5f * s8[2 * threadIdx.x + 1]);
}

// ---------------- argmin GEMM (packed f32x2, cp.async pipeline, A direct from h) ----------------
__device__ __forceinline__ void issue_stage(
    float (*AS)[16][128], float (*BS)[16][128],
    const float* __restrict__ hbase, const float* __restrict__ bt,
    int s, int tid) {
    int ct = s >> 4, dss = s & 15, buf = s & 1;
    int d0 = dss * 16, c0 = ct * 128;
    int row = tid >> 5, col = tid & 31;         // 512 cp16 ops, 2 per thread
#pragma unroll
    for (int k = 0; k < 2; k++) {
        int r = row + k * 8;
        cp16(&AS[buf][r][col * 4], hbase + (size_t)(d0 + r) * TLEN + col * 4);
        cp16(&BS[buf][r][col * 4], bt + (size_t)(d0 + r) * KCODES + c0 + col * 4);
    }
    CP_COMMIT();
}

__global__ __launch_bounds__(256, 2)
void argmin_kernel(const float* __restrict__ h_top, const float* __restrict__ h_bot) {
    __shared__ float AS[2][16][128];   // 16KB: [buf][dd][t]     (undup A)
    __shared__ float BS[2][16][128];   // 16KB: [buf][dd][code]

    int tid = threadIdx.x, lvl = blockIdx.y;
    int m0 = blockIdx.x * 128;
    int b  = m0 / TLEN, t0 = m0 % TLEN;
    int ty = tid >> 4, tx = tid & 15;
    const float* h  = lvl ? h_bot : h_top;
    const float* hbase = h + (size_t)b * DIM * TLEN + t0;
    const float* bt = g_bt + (size_t)lvl * DIM * KCODES;

    float best[8], b2[8];
    int   bidx[8];
#pragma unroll
    for (int i = 0; i < 8; i++) { best[i] = -FLT_MAX; b2[i] = -FLT_MAX; bidx[i] = 0; }

    issue_stage(AS, BS, hbase, bt, 0, tid);

    unsigned long long acc[8][4];

#pragma unroll 1
    for (int ct = 0; ct < 8; ct++) {
        const float2* cip = g_cninit + lvl * (KCODES / 2) + ((ct * 128 + tx * 8) >> 1);
        ulonglong2 ci01 = *(const ulonglong2*)cip;
        ulonglong2 ci23 = *(const ulonglong2*)(cip + 2);
#pragma unroll
        for (int i = 0; i < 8; i++) {
            acc[i][0] = ci01.x; acc[i][1] = ci01.y;
            acc[i][2] = ci23.x; acc[i][3] = ci23.y;
        }

#pragma unroll 1
        for (int dss = 0; dss < 16; dss++) {
            int s = ct * 16 + dss, buf = s & 1;
            if (s < 127) { issue_stage(AS, BS, hbase, bt, s + 1, tid); CP_WAIT1(); }
            else         { CP_WAIT0(); }
            __syncthreads();

#pragma unroll
            for (int dd = 0; dd < 16; dd++) {
                float4 a03 = *(const float4*)&AS[buf][dd][ty * 8];
                float4 a47 = *(const float4*)&AS[buf][dd][ty * 8 + 4];
                ulonglong2 b03 = *(const ulonglong2*)&BS[buf][dd][tx * 8];
                ulonglong2 b47 = *(const ulonglong2*)&BS[buf][dd][tx * 8 + 4];
                unsigned long long A8[8] = {
                    pk2(a03.x), pk2(a03.y), pk2(a03.z), pk2(a03.w),
                    pk2(a47.x), pk2(a47.y), pk2(a47.z), pk2(a47.w)};
#pragma unroll
                for (int i = 0; i < 8; i++) {
                    fma2(acc[i][0], A8[i], b03.x);
                    fma2(acc[i][1], A8[i], b03.y);
                    fma2(acc[i][2], A8[i], b47.x);
                    fma2(acc[i][3], A8[i], b47.y);
                }
            }
            __syncthreads();
        }

#pragma unroll
        for (int j = 0; j < 4; j++) {
            int ce = ct * 128 + tx * 8 + 2 * j;
#pragma unroll
            for (int i = 0; i < 8; i++) {
                float se, so;
                unpk2(acc[i][j], se, so);
                if (se > best[i]) { b2[i] = best[i]; best[i] = se; bidx[i] = ce; }
                else if (se > b2[i]) b2[i] = se;
                if (so > best[i]) { b2[i] = best[i]; best[i] = so; bidx[i] = ce + 1; }
                else if (so > b2[i]) b2[i] = so;
            }
        }
    }

    __syncthreads();
    float* sval = (float*)AS;
    int*   sidx = (int*)(sval + 2048);
    float* s2v  = (float*)BS;
#pragma unroll
    for (int i = 0; i < 8; i++) {
        int p = ty * 8 + i;
        sval[tx * 128 + p] = best[i];
        sidx[tx * 128 + p] = bidx[i];
        s2v[tx * 128 + p]  = b2[i];
    }
    __syncthreads();
    if (tid < 128) {
        float bv = sval[tid];
        int   bi = sidx[tid];
        float bs = s2v[tid];
#pragma unroll
        for (int x = 1; x < 16; x++) {
            float v  = sval[x * 128 + tid];
            int   ii = sidx[x * 128 + tid];
            float v2 = s2v[x * 128 + tid];
            if (v > bv || (v == bv && ii < bi)) { bs = fmaxf(bv, v2); bv = v; bi = ii; }
            else                                 bs = fmaxf(bs, v);
        }
        g_idx[lvl][m0 + tid] = bi;
        if (bv - bs < TAU_S) {
            int pos = atomicAdd(&g_refine_count[lvl], 1);
            g_refine_list[lvl][pos] = m0 + tid;
        }
    }
}

// ---------------- kernel: double-f32 exact refinement of near-ties (FMA pipe) ----------------
// Distance per code accumulated as unevaluated (hi,lo) pair; all error terms captured
// via TwoSum/TwoProd -> effective precision ~1e-10 absolute, resolving every gap f64 did.
__global__ __launch_bounds__(256)
void refine_kernel(const float* __restrict__ h_top, const float* __restrict__ h_bot) {
    int lvl = blockIdx.y;
    const float* h = lvl ? h_bot : h_top;
    const float* bt = g_bt + (size_t)lvl * DIM * KCODES;
    int cnt = g_refine_count[lvl];

    __shared__ float xs[DIM];
    __shared__ float rh[256], rl[256];
    __shared__ int   rix[256];

    int tid = threadIdx.x;

    for (int e = blockIdx.x; e < cnt; e += gridDim.x) {
        int p = g_refine_list[lvl][e];
        int b = p / TLEN, t = p % TLEN;
        __syncthreads();   // protect xs/reduce arrays across outer iterations
        xs[tid] = h[((size_t)b * DIM + tid) * TLEN + t];
        __syncthreads();

        float bh = FLT_MAX, bl = 0.f;
        int   bi = 0;
#pragma unroll 1
        for (int k = 0; k < 4; k++) {
            int c = k * 256 + tid;                 // ascending per thread
            float hi = 0.f, lo = 0.f;
#pragma unroll 4
            for (int d = 0; d < DIM; d++) {
                float ev = bt[(size_t)d * KCODES + c];   // coalesced across tid
                float x  = xs[d];
                // TwoSum: s + err == x - ev exactly
                float s  = x - ev;
                float bb = s - x;
                float err = (x - (s - bb)) + ((-ev) - bb);
                // TwoProd: pq + pe == s*s exactly
                float pq = s * s;
                float pe = fmaf(s, s, -pq);
                // (s+err)^2 = pq + (pe + 2 s err + err^2)
                float cross = fmaf(2.f * s, err, fmaf(err, err, pe));
                // compensated accumulate pq into (hi, lo)
                float t1  = hi + pq;
                float bb2 = t1 - hi;
                float e2  = (hi - (t1 - bb2)) + (pq - bb2);
                hi = t1;
                lo += e2 + cross;
            }
            // renormalize
            float th = hi + lo;
            float tl = lo - (th - hi);
            if (th < bh || (th == bh && tl < bl)) { bh = th; bl = tl; bi = c; }
        }
        rh[tid] = bh; rl[tid] = bl; rix[tid] = bi;
        __syncthreads();
#pragma unroll
        for (int s = 128; s; s >>= 1) {
            if (tid < s) {
                float oh = rh[tid + s], ol = rl[tid + s];
                int   oi = rix[tid + s];
                float mh = rh[tid], ml = rl[tid];
                int   mi = rix[tid];
                if (oh < mh || (oh == mh && (ol < ml || (ol == ml && oi < mi)))) {
                    rh[tid] = oh; rl[tid] = ol; rix[tid] = oi;
                }
            }
            __syncthreads();
        }
        if (tid == 0) g_idx[lvl][p] = rix[0];
    }
}

// ---------------- kernel: gather z_q + per-block loss partials ----------------
__global__ __launch_bounds__(256)
void gather_kernel(const float* __restrict__ h_top, const float* __restrict__ h_bot,
                   const float* __restrict__ cb_top, const float* __restrict__ cb_bot,
                   float* __restrict__ out) {
    int lvl = blockIdx.z;
    const float* h  = lvl ? h_bot  : h_top;
    const float* cb = lvl ? cb_bot : cb_top;
    float* z = out + (size_t)lvl * NELEM;

    int b = blockIdx.y;
    int t0 = blockIdx.x * 32;
    int tid = threadIdx.x;

    __shared__ int   sidx[32];
    __shared__ float sh[32 * 33];
    __shared__ float red[256];

    if (tid < 32) sidx[tid] = g_idx[lvl][b * TLEN + t0 + tid];
    __syncthreads();

    float lacc = 0.f;
    int j2 = tid >> 3, l8 = tid & 7;

    for (int dc = 0; dc < DIM; dc += 32) {
        float4 v = *(const float4*)(cb + (size_t)sidx[j2] * DIM + dc + l8 * 4);
        sh[(l8 * 4 + 0) * 33 + j2] = v.x;
        sh[(l8 * 4 + 1) * 33 + j2] = v.y;
        sh[(l8 * 4 + 2) * 33 + j2] = v.z;
        sh[(l8 * 4 + 3) * 33 + j2] = v.w;
        __syncthreads();
#pragma unroll
        for (int it = 0; it < 4; it++) {
            int i = tid + it * 256;
            int dl = i >> 5, j = i & 31;
            size_t off = ((size_t)b * DIM + dc + dl) * TLEN + t0 + j;
            float zz = sh[dl * 33 + j];
            z[off] = zz;
            float e = h[off] - zz;
            lacc = fmaf(e, e, lacc);
        }
        __syncthreads();
    }

    red[tid] = lacc;
    __syncthreads();
#pragma unroll
    for (int s = 128; s; s >>= 1) {
        if (tid < s) red[tid] += red[tid + s];
        __syncthreads();
    }
    if (tid == 0) g_partial[lvl][blockIdx.y * (TLEN / 32) + blockIdx.x] = red[0];
}

// ---------------- kernel: finalize scalars ----------------
__global__ __launch_bounds__(1024)
void finalize_kernel(float* __restrict__ out) {
    __shared__ int   hist[KCODES];
    __shared__ float red[1024];
    int tid = threadIdx.x;

    float sums[2];
#pragma unroll
    for (int lvl = 0; lvl < 2; lvl++) {
        red[tid] = g_partial[lvl][tid];
        __syncthreads();
        for (int s = 512; s; s >>= 1) {
            if (tid < s) red[tid] += red[tid + s];
            __syncthreads();
        }
        sums[lvl] = red[0];
        __syncthreads();
    }
    float loss = sums[0] * (1.f / (float)NELEM) + sums[1] * (1.f / (float)NELEM);

    float ppl[2];
#pragma unroll
    for (int lvl = 0; lvl < 2; lvl++) {
        hist[tid] = 0;
        __syncthreads();
#pragma unroll
        for (int i = 0; i < NPTS / 1024; i++)
            atomicAdd(&hist[g_idx[lvl][i * 1024 + tid]], 1);
        __syncthreads();
        float p = (float)hist[tid] * (1.f / (float)NPTS);
        red[tid] = p * logf(p + 1e-10f);
        __syncthreads();
        for (int s = 512; s; s >>= 1) {
            if (tid < s) red[tid] += red[tid + s];
            __syncthreads();
        }
        ppl[lvl] = expf(-red[0]);
        __syncthreads();
    }

    if (tid == 0) {
        size_t base = (size_t)2 * NELEM;
        out[base + 0] = loss;
        out[base + 1] = loss;
        out[base + 2] = ppl[0];
        out[base + 3] = ppl[1];
    }
}

// ---------------- launcher ----------------
extern "C" void kernel_launch(void* const* d_in, const int* in_sizes, int n_in,
                              void* d_out, int out_size) {
    const float* h_top  = (const float*)d_in[0];
    const float* h_bot  = (const float*)d_in[1];
    const float* cb_top = (const float*)d_in[2];
    const float* cb_bot = (const float*)d_in[3];
    float* out = (float*)d_out;

    btrans_kernel<<<dim3(KCODES / 32, DIM / 32, LEVELS), 256>>>(cb_top, cb_bot);
    cnorm_kernel <<<dim3(KCODES / 8, LEVELS), 256>>>(cb_top, cb_bot);
    argmin_kernel<<<dim3(NPTS / 128, LEVELS), 256>>>(h_top, h_bot);
    refine_kernel<<<dim3(512, LEVELS), 256>>>(h_top, h_bot);
    gather_kernel<<<dim3(TLEN / 32, BATCH, LEVELS), 256>>>(h_top, h_bot, cb_top, cb_bot, out);
    finalize_kernel<<<1, 1024>>>(out);
}

// round 7
// speedup vs baseline: 1.8230x; 1.0170x over previous
#include <cuda_runtime.h>
#include <cstdint>
#include <cfloat>

#define LEVELS 2
#define BATCH  16
#define DIM    256
#define TLEN   2048
#define NPTS   (BATCH * TLEN)       // 32768 points per level
#define KCODES 1024
#define NELEM  (BATCH * DIM * TLEN) // 8388608 per level
#define GATHER_BLOCKS (BATCH * (TLEN / 32))
#define TAU_S  0.004f               // ~30x combined 1-sigma error; 5x the 6-sigma bound

// ---------------- scratch (no allocations allowed) ----------------
__device__ float  g_bt[(size_t)LEVELS * DIM * KCODES];     // codebook transposed: [lvl][d][c]
__device__ float2 g_cninit[LEVELS * (KCODES / 2)];         // packed (-cn/2) pairs
__device__ float  g_partial[LEVELS][GATHER_BLOCKS];
__device__ int    g_idx[LEVELS][NPTS];
__device__ int    g_refine_count[LEVELS];
__device__ int    g_refine_list[LEVELS][NPTS];

// ---------------- f32x2 / async helpers ----------------
__device__ __forceinline__ unsigned long long pk2(float a) {
    unsigned long long r;
    unsigned int u = __float_as_uint(a);
    asm("mov.b64 %0, {%1, %1};" : "=l"(r) : "r"(u));
    return r;
}
__device__ __forceinline__ void fma2(unsigned long long& acc,
                                     unsigned long long a,
                                     unsigned long long b) {
    asm("fma.rn.f32x2 %0, %1, %2, %0;" : "+l"(acc) : "l"(a), "l"(b));
}
__device__ __forceinline__ void unpk2(unsigned long long v, float& lo, float& hi) {
    unsigned int l, h;
    asm("mov.b64 {%0, %1}, %2;" : "=r"(l), "=r"(h) : "l"(v));
    lo = __uint_as_float(l);
    hi = __uint_as_float(h);
}
__device__ __forceinline__ void cp16(void* dst, const void* src) {
    unsigned s = (unsigned)__cvta_generic_to_shared(dst);
    asm volatile("cp.async.cg.shared.global [%0], [%1], 16;" :: "r"(s), "l"(src) : "memory");
}
#define CP_COMMIT() asm volatile("cp.async.commit_group;" ::: "memory")
#define CP_WAIT1()  asm volatile("cp.async.wait_group 1;" ::: "memory")
#define CP_WAIT0()  asm volatile("cp.async.wait_group 0;" ::: "memory")

// ---------------- kernel: transpose codebook to [d][c] ----------------
__global__ __launch_bounds__(256)
void btrans_kernel(const float* __restrict__ cb_top, const float* __restrict__ cb_bot) {
    __shared__ float s[32][33];
    int lvl = blockIdx.z;
    const float* cb = lvl ? cb_bot : cb_top;
    int c0 = blockIdx.x * 32, d0 = blockIdx.y * 32;
    int lx = threadIdx.x & 31, ly = threadIdx.x >> 5;   // ly 0..7
#pragma unroll
    for (int k = 0; k < 4; k++)
        s[ly + 8 * k][lx] = cb[(size_t)(c0 + ly + 8 * k) * DIM + d0 + lx];
    __syncthreads();
#pragma unroll
    for (int k = 0; k < 4; k++)
        g_bt[((size_t)lvl * DIM + d0 + ly + 8 * k) * KCODES + c0 + lx] = s[lx][ly + 8 * k];
}

// ---------------- kernel: codebook norms -> packed -cn/2 + counter reset ----------------
__global__ __launch_bounds__(256)
void cnorm_kernel(const float* __restrict__ cb_top, const float* __restrict__ cb_bot) {
    __shared__ float s8[8];
    int lvl = blockIdx.y;
    if (blockIdx.x == 0 && threadIdx.x == 0) g_refine_count[lvl] = 0;
    const float* cb = lvl ? cb_bot : cb_top;
    int w = threadIdx.x >> 5, lane = threadIdx.x & 31;
    int c = blockIdx.x * 8 + w;
    const float* row = cb + (size_t)c * DIM;
    float sacc = 0.f;
#pragma unroll
    for (int i = 0; i < DIM / 32; i++) {
        float v = row[i * 32 + lane];
        sacc = fmaf(v, v, sacc);
    }
#pragma unroll
    for (int o = 16; o; o >>= 1) sacc += __shfl_down_sync(0xffffffffu, sacc, o);
    if (lane == 0) s8[w] = sacc;
    __syncthreads();
    if (threadIdx.x < 4)
        g_cninit[lvl * (KCODES / 2) + blockIdx.x * 4 + threadIdx.x] =
            make_float2(-0.5f * s8[2 * threadIdx.x], -0.5f * s8[2 * threadIdx.x + 1]);
}

// ---------------- argmin GEMM (packed f32x2, cp.async pipeline, A direct from h) ----------------
__device__ __forceinline__ void issue_stage(
    float (*AS)[16][128], float (*BS)[16][128],
    const float* __restrict__ hbase, const float* __restrict__ bt,
    int s, int tid) {
    int ct = s >> 4, dss = s & 15, buf = s & 1;
    int d0 = dss * 16, c0 = ct * 128;
    int row = tid >> 5, col = tid & 31;         // 512 cp16 ops, 2 per thread
#pragma unroll
    for (int k = 0; k < 2; k++) {
        int r = row + k * 8;
        cp16(&AS[buf][r][col * 4], hbase + (size_t)(d0 + r) * TLEN + col * 4);
        cp16(&BS[buf][r][col * 4], bt + (size_t)(d0 + r) * KCODES + c0 + col * 4);
    }
    CP_COMMIT();
}

__global__ __launch_bounds__(256, 2)
void argmin_kernel(const float* __restrict__ h_top, const float* __restrict__ h_bot) {
    __shared__ float AS[2][16][128];   // 16KB: [buf][dd][t]     (undup A)
    __shared__ float BS[2][16][128];   // 16KB: [buf][dd][code]

    int tid = threadIdx.x, lvl = blockIdx.y;
    int m0 = blockIdx.x * 128;
    int b  = m0 / TLEN, t0 = m0 % TLEN;
    int ty = tid >> 4, tx = tid & 15;
    const float* h  = lvl ? h_bot : h_top;
    const float* hbase = h + (size_t)b * DIM * TLEN + t0;
    const float* bt = g_bt + (size_t)lvl * DIM * KCODES;

    float best[8], b2[8];
    int   bidx[8];
#pragma unroll
    for (int i = 0; i < 8; i++) { best[i] = -FLT_MAX; b2[i] = -FLT_MAX; bidx[i] = 0; }

    issue_stage(AS, BS, hbase, bt, 0, tid);

    unsigned long long acc[8][4];

#pragma unroll 1
    for (int ct = 0; ct < 8; ct++) {
        const float2* cip = g_cninit + lvl * (KCODES / 2) + ((ct * 128 + tx * 8) >> 1);
        ulonglong2 ci01 = *(const ulonglong2*)cip;
        ulonglong2 ci23 = *(const ulonglong2*)(cip + 2);
#pragma unroll
        for (int i = 0; i < 8; i++) {
            acc[i][0] = ci01.x; acc[i][1] = ci01.y;
            acc[i][2] = ci23.x; acc[i][3] = ci23.y;
        }

#pragma unroll 1
        for (int dss = 0; dss < 16; dss++) {
            int s = ct * 16 + dss, buf = s & 1;
            if (s < 127) { issue_stage(AS, BS, hbase, bt, s + 1, tid); CP_WAIT1(); }
            else         { CP_WAIT0(); }
            __syncthreads();

#pragma unroll
            for (int dd = 0; dd < 16; dd++) {
                float4 a03 = *(const float4*)&AS[buf][dd][ty * 8];
                float4 a47 = *(const float4*)&AS[buf][dd][ty * 8 + 4];
                ulonglong2 b03 = *(const ulonglong2*)&BS[buf][dd][tx * 8];
                ulonglong2 b47 = *(const ulonglong2*)&BS[buf][dd][tx * 8 + 4];
                unsigned long long A8[8] = {
                    pk2(a03.x), pk2(a03.y), pk2(a03.z), pk2(a03.w),
                    pk2(a47.x), pk2(a47.y), pk2(a47.z), pk2(a47.w)};
#pragma unroll
                for (int i = 0; i < 8; i++) {
                    fma2(acc[i][0], A8[i], b03.x);
                    fma2(acc[i][1], A8[i], b03.y);
                    fma2(acc[i][2], A8[i], b47.x);
                    fma2(acc[i][3], A8[i], b47.y);
                }
            }
            __syncthreads();
        }

#pragma unroll
        for (int j = 0; j < 4; j++) {
            int ce = ct * 128 + tx * 8 + 2 * j;
#pragma unroll
            for (int i = 0; i < 8; i++) {
                float se, so;
                unpk2(acc[i][j], se, so);
                if (se > best[i]) { b2[i] = best[i]; best[i] = se; bidx[i] = ce; }
                else if (se > b2[i]) b2[i] = se;
                if (so > best[i]) { b2[i] = best[i]; best[i] = so; bidx[i] = ce + 1; }
                else if (so > b2[i]) b2[i] = so;
            }
        }
    }

    __syncthreads();
    float* sval = (float*)AS;
    int*   sidx = (int*)(sval + 2048);
    float* s2v  = (float*)BS;
#pragma unroll
    for (int i = 0; i < 8; i++) {
        int p = ty * 8 + i;
        sval[tx * 128 + p] = best[i];
        sidx[tx * 128 + p] = bidx[i];
        s2v[tx * 128 + p]  = b2[i];
    }
    __syncthreads();
    if (tid < 128) {
        float bv = sval[tid];
        int   bi = sidx[tid];
        float bs = s2v[tid];
#pragma unroll
        for (int x = 1; x < 16; x++) {
            float v  = sval[x * 128 + tid];
            int   ii = sidx[x * 128 + tid];
            float v2 = s2v[x * 128 + tid];
            if (v > bv || (v == bv && ii < bi)) { bs = fmaxf(bv, v2); bv = v; bi = ii; }
            else                                 bs = fmaxf(bs, v);
        }
        g_idx[lvl][m0 + tid] = bi;
        if (bv - bs < TAU_S) {
            int pos = atomicAdd(&g_refine_count[lvl], 1);
            g_refine_list[lvl][pos] = m0 + tid;
        }
    }
}

// ---------------- kernel: double-f32 exact refinement (1 point/block, 1 code/thread) ----------------
__global__ __launch_bounds__(1024)
void refine_kernel(const float* __restrict__ h_top, const float* __restrict__ h_bot) {
    int lvl = blockIdx.y;
    const float* h = lvl ? h_bot : h_top;
    const float* bt = g_bt + (size_t)lvl * DIM * KCODES;
    int cnt = g_refine_count[lvl];

    __shared__ float xs[DIM];
    __shared__ float rh[1024], rl[1024];
    __shared__ int   rix[1024];

    int tid = threadIdx.x;
    int c = tid;                                // one code per thread

    for (int e = blockIdx.x; e < cnt; e += gridDim.x) {
        int p = g_refine_list[lvl][e];
        int b = p / TLEN, t = p % TLEN;
        __syncthreads();   // protect xs/reduce arrays across outer iterations
        if (tid < DIM)
            xs[tid] = h[((size_t)b * DIM + tid) * TLEN + t];
        __syncthreads();

        float hi = 0.f, lo = 0.f;
#pragma unroll 8
        for (int d = 0; d < DIM; d++) {
            float ev = bt[(size_t)d * KCODES + c];   // coalesced across tid, L2-resident
            float x  = xs[d];
            // TwoSum: s + err == x - ev exactly
            float s  = x - ev;
            float bb = s - x;
            float err = (x - (s - bb)) + ((-ev) - bb);
            // TwoProd: pq + pe == s*s exactly
            float pq = s * s;
            float pe = fmaf(s, s, -pq);
            // (s+err)^2 = pq + (pe + 2 s err + err^2)
            float cross = fmaf(2.f * s, err, fmaf(err, err, pe));
            // compensated accumulate pq into (hi, lo)
            float t1  = hi + pq;
            float bb2 = t1 - hi;
            float e2  = (hi - (t1 - bb2)) + (pq - bb2);
            hi = t1;
            lo += e2 + cross;
        }
        // renormalize
        float th = hi + lo;
        float tl = lo - (th - hi);

        rh[tid] = th; rl[tid] = tl; rix[tid] = c;
        __syncthreads();
#pragma unroll
        for (int s = 512; s; s >>= 1) {
            if (tid < s) {
                float oh = rh[tid + s], ol = rl[tid + s];
                int   oi = rix[tid + s];
                float mh = rh[tid], ml = rl[tid];
                int   mi = rix[tid];
                if (oh < mh || (oh == mh && (ol < ml || (ol == ml && oi < mi)))) {
                    rh[tid] = oh; rl[tid] = ol; rix[tid] = oi;
                }
            }
            __syncthreads();
        }
        if (tid == 0) g_idx[lvl][p] = rix[0];
    }
}

// ---------------- kernel: gather z_q + per-block loss partials ----------------
__global__ __launch_bounds__(256)
void gather_kernel(const float* __restrict__ h_top, const float* __restrict__ h_bot,
                   const float* __restrict__ cb_top, const float* __restrict__ cb_bot,
                   float* __restrict__ out) {
    int lvl = blockIdx.z;
    const float* h  = lvl ? h_bot  : h_top;
    const float* cb = lvl ? cb_bot : cb_top;
    float* z = out + (size_t)lvl * NELEM;

    int b = blockIdx.y;
    int t0 = blockIdx.x * 32;
    int tid = threadIdx.x;

    __shared__ int   sidx[32];
    __shared__ float sh[32 * 33];
    __shared__ float red[256];

    if (tid < 32) sidx[tid] = g_idx[lvl][b * TLEN + t0 + tid];
    __syncthreads();

    float lacc = 0.f;
    int j2 = tid >> 3, l8 = tid & 7;

    for (int dc = 0; dc < DIM; dc += 32) {
        float4 v = *(const float4*)(cb + (size_t)sidx[j2] * DIM + dc + l8 * 4);
        sh[(l8 * 4 + 0) * 33 + j2] = v.x;
        sh[(l8 * 4 + 1) * 33 + j2] = v.y;
        sh[(l8 * 4 + 2) * 33 + j2] = v.z;
        sh[(l8 * 4 + 3) * 33 + j2] = v.w;
        __syncthreads();
#pragma unroll
        for (int it = 0; it < 4; it++) {
            int i = tid + it * 256;
            int dl = i >> 5, j = i & 31;
            size_t off = ((size_t)b * DIM + dc + dl) * TLEN + t0 + j;
            float zz = sh[dl * 33 + j];
            z[off] = zz;
            float e = h[off] - zz;
            lacc = fmaf(e, e, lacc);
        }
        __syncthreads();
    }

    red[tid] = lacc;
    __syncthreads();
#pragma unroll
    for (int s = 128; s; s >>= 1) {
        if (tid < s) red[tid] += red[tid + s];
        __syncthreads();
    }
    if (tid == 0) g_partial[lvl][blockIdx.y * (TLEN / 32) + blockIdx.x] = red[0];
}

// ---------------- kernel: finalize scalars ----------------
__global__ __launch_bounds__(1024)
void finalize_kernel(float* __restrict__ out) {
    __shared__ int   hist[KCODES];
    __shared__ float red[1024];
    int tid = threadIdx.x;

    float sums[2];
#pragma unroll
    for (int lvl = 0; lvl < 2; lvl++) {
        red[tid] = g_partial[lvl][tid];
        __syncthreads();
        for (int s = 512; s; s >>= 1) {
            if (tid < s) red[tid] += red[tid + s];
            __syncthreads();
        }
        sums[lvl] = red[0];
        __syncthreads();
    }
    float loss = sums[0] * (1.f / (float)NELEM) + sums[1] * (1.f / (float)NELEM);

    float ppl[2];
#pragma unroll
    for (int lvl = 0; lvl < 2; lvl++) {
        hist[tid] = 0;
        __syncthreads();
#pragma unroll
        for (int i = 0; i < NPTS / 1024; i++)
            atomicAdd(&hist[g_idx[lvl][i * 1024 + tid]], 1);
        __syncthreads();
        float p = (float)hist[tid] * (1.f / (float)NPTS);
        red[tid] = p * logf(p + 1e-10f);
        __syncthreads();
        for (int s = 512; s; s >>= 1) {
            if (tid < s) red[tid] += red[tid + s];
            __syncthreads();
        }
        ppl[lvl] = expf(-red[0]);
        __syncthreads();
    }

    if (tid == 0) {
        size_t base = (size_t)2 * NELEM;
        out[base + 0] = loss;
        out[base + 1] = loss;
        out[base + 2] = ppl[0];
        out[base + 3] = ppl[1];
    }
}

// ---------------- launcher ----------------
extern "C" void kernel_launch(void* const* d_in, const int* in_sizes, int n_in,
                              void* d_out, int out_size) {
    const float* h_top  = (const float*)d_in[0];
    const float* h_bot  = (const float*)d_in[1];
    const float* cb_top = (const float*)d_in[2];
    const float* cb_bot = (const float*)d_in[3];
    float* out = (float*)d_out;

    btrans_kernel<<<dim3(KCODES / 32, DIM / 32, LEVELS), 256>>>(cb_top, cb_bot);
    cnorm_kernel <<<dim3(KCODES / 8, LEVELS), 256>>>(cb_top, cb_bot);
    argmin_kernel<<<dim3(NPTS / 128, LEVELS), 256>>>(h_top, h_bot);
    refine_kernel<<<dim3(512, LEVELS), 1024>>>(h_top, h_bot);
    gather_kernel<<<dim3(TLEN / 32, BATCH, LEVELS), 256>>>(h_top, h_bot, cb_top, cb_bot, out);
    finalize_kernel<<<1, 1024>>>(out);
}

// round 9
// speedup vs baseline: 2.6600x; 1.4592x over previous
#include <cuda_runtime.h>
#include <cuda_bf16.h>
#include <cstdint>
#include <cfloat>

#define LEVELS 2
#define BATCH  16
#define DIM    256
#define TLEN   2048
#define NPTS   (BATCH * TLEN)       // 32768 points per level
#define KCODES 1024
#define NELEM  (BATCH * DIM * TLEN) // 8388608 per level
#define GATHER_BLOCKS (BATCH * (TLEN / 32))
#define TAU_S  0.004f               // ~11 sigma of split-bf16 HMMA error in s-space

// ---------------- scratch (no allocations allowed) ----------------
__device__ float    g_bt[(size_t)LEVELS * DIM * KCODES];   // codebook transposed (refine)
__device__ float2   g_cninit[LEVELS * (KCODES / 2)];       // packed (-cn/2) pairs
__device__ float    g_partial[LEVELS][GATHER_BLOCKS];
__device__ int      g_idx[LEVELS][NPTS];
__device__ int      g_refine_count[LEVELS];
__device__ int      g_refine_list[LEVELS][NPTS];
// bf16 splits packed as u32 pairs (elem 2d in low half): [p][d] and [c][d]
__device__ unsigned g_xhi[(size_t)LEVELS * NPTS * (DIM / 2)];
__device__ unsigned g_xlo[(size_t)LEVELS * NPTS * (DIM / 2)];
__device__ unsigned g_ehi[(size_t)LEVELS * KCODES * (DIM / 2)];
__device__ unsigned g_elo[(size_t)LEVELS * KCODES * (DIM / 2)];

// ---------------- helpers ----------------
__device__ __forceinline__ void cp16(void* dst, const void* src) {
    unsigned s = (unsigned)__cvta_generic_to_shared(dst);
    asm volatile("cp.async.cg.shared.global [%0], [%1], 16;" :: "r"(s), "l"(src) : "memory");
}
#define CP_COMMIT() asm volatile("cp.async.commit_group;" ::: "memory")
#define CP_WAIT1()  asm volatile("cp.async.wait_group 1;" ::: "memory")
#define CP_WAIT0()  asm volatile("cp.async.wait_group 0;" ::: "memory")

__device__ __forceinline__ void lda4(uint32_t r[4], uint32_t addr) {
    asm volatile("ldmatrix.sync.aligned.m8n8.x4.shared.b16 {%0,%1,%2,%3}, [%4];"
                 : "=r"(r[0]), "=r"(r[1]), "=r"(r[2]), "=r"(r[3]) : "r"(addr));
}
// B tile smem is [n][k] (row=code, col=dim) -> NON-trans ldmatrix delivers the
// mma B fragment directly (lane l: B_smem[n=l/4][k=2*(l%4)+{0,1}]).
__device__ __forceinline__ void ldb2(uint32_t r[2], uint32_t addr) {
    asm volatile("ldmatrix.sync.aligned.m8n8.x2.shared.b16 {%0,%1}, [%2];"
                 : "=r"(r[0]), "=r"(r[1]) : "r"(addr));
}
__device__ __forceinline__ void mma16816(float d[4], const uint32_t a[4], const uint32_t b[2]) {
    asm volatile("mma.sync.aligned.m16n8k16.row.col.f32.bf16.bf16.f32 "
                 "{%0,%1,%2,%3}, {%4,%5,%6,%7}, {%8,%9}, {%0,%1,%2,%3};"
                 : "+f"(d[0]), "+f"(d[1]), "+f"(d[2]), "+f"(d[3])
                 : "r"(a[0]), "r"(a[1]), "r"(a[2]), "r"(a[3]), "r"(b[0]), "r"(b[1]));
}

// ---------------- kernel: split+transpose h -> x_hi/x_lo bf16 [lvl][p][d] ----------------
__global__ __launch_bounds__(256)
void xsplit_kernel(const float* __restrict__ h_top, const float* __restrict__ h_bot) {
    __shared__ float s[32][65];
    int z = blockIdx.z, lvl = z >> 4, b = z & 15;
    const float* h = lvl ? h_bot : h_top;
    int t0 = blockIdx.x * 32, d0 = blockIdx.y * 64;
    int tid = threadIdx.x, lane = tid & 31, w = tid >> 5;
#pragma unroll
    for (int k = 0; k < 8; k++) {
        int dl = w + 8 * k;
        s[lane][dl] = h[((size_t)b * DIM + d0 + dl) * TLEN + t0 + lane];
    }
    __syncthreads();
    int pl = tid >> 3, q = tid & 7;
    int p = b * TLEN + t0 + pl;
    size_t rowbase = ((size_t)lvl * NPTS + p) * (DIM / 2) + (d0 >> 1);
#pragma unroll
    for (int k = 0; k < 4; k++) {
        int d2 = q + 8 * k;
        float v0 = s[pl][2 * d2], v1 = s[pl][2 * d2 + 1];
        __nv_bfloat16 h0 = __float2bfloat16(v0), h1 = __float2bfloat16(v1);
        __nv_bfloat16 l0 = __float2bfloat16(v0 - __bfloat162float(h0));
        __nv_bfloat16 l1 = __float2bfloat16(v1 - __bfloat162float(h1));
        g_xhi[rowbase + d2] = ((unsigned)__bfloat16_as_ushort(h1) << 16) | __bfloat16_as_ushort(h0);
        g_xlo[rowbase + d2] = ((unsigned)__bfloat16_as_ushort(l1) << 16) | __bfloat16_as_ushort(l0);
    }
}

// ---------------- kernel: codebook split + (-cn/2) + counter reset ----------------
__global__ __launch_bounds__(256)
void ecnorm_kernel(const float* __restrict__ cb_top, const float* __restrict__ cb_bot) {
    __shared__ float s8[8];
    int lvl = blockIdx.y;
    if (blockIdx.x == 0 && threadIdx.x == 0) g_refine_count[lvl] = 0;
    const float* cb = lvl ? cb_bot : cb_top;
    int w = threadIdx.x >> 5, lane = threadIdx.x & 31;
    int c = blockIdx.x * 8 + w;
    const float* row = cb + (size_t)c * DIM;
    size_t rowbase = ((size_t)lvl * KCODES + c) * (DIM / 2);
    float sacc = 0.f;
#pragma unroll
    for (int k = 0; k < 4; k++) {
        int d2 = lane + 32 * k;
        float v0 = row[2 * d2], v1 = row[2 * d2 + 1];
        sacc = fmaf(v0, v0, sacc);
        sacc = fmaf(v1, v1, sacc);
        __nv_bfloat16 h0 = __float2bfloat16(v0), h1 = __float2bfloat16(v1);
        __nv_bfloat16 l0 = __float2bfloat16(v0 - __bfloat162float(h0));
        __nv_bfloat16 l1 = __float2bfloat16(v1 - __bfloat162float(h1));
        g_ehi[rowbase + d2] = ((unsigned)__bfloat16_as_ushort(h1) << 16) | __bfloat16_as_ushort(h0);
        g_elo[rowbase + d2] = ((unsigned)__bfloat16_as_ushort(l1) << 16) | __bfloat16_as_ushort(l0);
    }
#pragma unroll
    for (int o = 16; o; o >>= 1) sacc += __shfl_down_sync(0xffffffffu, sacc, o);
    if (lane == 0) s8[w] = sacc;
    __syncthreads();
    if (threadIdx.x < 4)
        g_cninit[lvl * (KCODES / 2) + blockIdx.x * 4 + threadIdx.x] =
            make_float2(-0.5f * s8[2 * threadIdx.x], -0.5f * s8[2 * threadIdx.x + 1]);
}

// ---------------- kernel: transpose codebook to [d][c] (refine uses it) ----------------
__global__ __launch_bounds__(256)
void btrans_kernel(const float* __restrict__ cb_top, const float* __restrict__ cb_bot) {
    __shared__ float s[32][33];
    int lvl = blockIdx.z;
    const float* cb = lvl ? cb_bot : cb_top;
    int c0 = blockIdx.x * 32, d0 = blockIdx.y * 32;
    int lx = threadIdx.x & 31, ly = threadIdx.x >> 5;
#pragma unroll
    for (int k = 0; k < 4; k++)
        s[ly + 8 * k][lx] = cb[(size_t)(c0 + ly + 8 * k) * DIM + d0 + lx];
    __syncthreads();
#pragma unroll
    for (int k = 0; k < 4; k++)
        g_bt[((size_t)lvl * DIM + d0 + ly + 8 * k) * KCODES + c0 + lx] = s[lx][ly + 8 * k];
}

// ---------------- argmin GEMM via mma.sync bf16 (split-f32 emulation) ----------------
// smem: A_hi 64KB | A_lo 64KB | B ring 3 x 10KB (rows padded to 80B)
#define SM_AHI 0
#define SM_ALO 65536
#define SM_B   131072
#define SM_RED 131072            // reduce scratch reuses B ring after mainloop
#define ARG_SMEM (131072 + 3 * 10240)

__device__ __forceinline__ void issueB(char* smem, int s, int tid, size_t L) {
    int nt = s >> 4, ch = s & 15, buf = s % 3;
    int row = tid >> 1, sg = tid & 1;
    char* bb = smem + SM_B + buf * 10240;
    size_t src = (L + nt * 128 + row) * (size_t)128 + ch * 8 + sg * 4;
    cp16(bb + row * 80 + sg * 16,      &g_ehi[src]);
    cp16(bb + row * 80 + 32 + sg * 16, &g_elo[src]);
    CP_COMMIT();
}

__global__ __launch_bounds__(256, 1)
void argmin_kernel() {
    extern __shared__ __align__(128) char smem[];
    int tid = threadIdx.x, lane = tid & 31, wid = tid >> 5;
    int wm = wid >> 1, wn = wid & 1;
    int lvl = blockIdx.y;
    int m0 = blockIdx.x * 128;
    size_t XL = (size_t)lvl * NPTS;
    size_t EL = (size_t)lvl * KCODES;
    uint32_t sb = (uint32_t)__cvta_generic_to_shared(smem);

    // ---- prologue: A (hi+lo) into swizzled resident smem, then B chunk 0 ----
#pragma unroll
    for (int i = 0; i < 16; i++) {
        int idx = tid + i * 256;            // 4096 segs per part
        int row = idx >> 5, seg = idx & 31;
        int soff = ((seg ^ (row & 7)) << 4);
        size_t src = (XL + m0 + row) * (size_t)128 + seg * 4;
        cp16(smem + SM_AHI + row * 512 + soff, &g_xhi[src]);
        cp16(smem + SM_ALO + row * 512 + soff, &g_xlo[src]);
    }
    CP_COMMIT();
    issueB(smem, 0, tid, EL);

    float tb[4], t2[4];
    int   ti[4];
#pragma unroll
    for (int r = 0; r < 4; r++) { tb[r] = -FLT_MAX; t2[r] = -FLT_MAX; ti[r] = 0; }

#pragma unroll 1
    for (int nt = 0; nt < 8; nt++) {
        // init accumulators with -cn/2 (per-column)
        float acc[2][8][4];
#pragma unroll
        for (int j = 0; j < 8; j++) {
            int c0 = nt * 128 + wn * 64 + j * 8 + (lane & 3) * 2;
            float2 ci = g_cninit[lvl * (KCODES / 2) + (c0 >> 1)];
#pragma unroll
            for (int mi = 0; mi < 2; mi++) {
                acc[mi][j][0] = ci.x; acc[mi][j][1] = ci.y;
                acc[mi][j][2] = ci.x; acc[mi][j][3] = ci.y;
            }
        }

#pragma unroll 1
        for (int ch = 0; ch < 16; ch++) {
            int s = nt * 16 + ch;
            if (s < 127) { issueB(smem, s + 1, tid, EL); CP_WAIT1(); }
            else         { CP_WAIT0(); }
            __syncthreads();
            uint32_t bb = sb + SM_B + (s % 3) * 10240;

            // ldmatrix A fragments (2 m-tiles x hi/lo)
            uint32_t ah[2][4], al[2][4];
#pragma unroll
            for (int mi = 0; mi < 2; mi++) {
                int p = wm * 32 + mi * 16 + (lane & 7) + ((lane >> 3) & 1) * 8;
                int seg = ch * 2 + (lane >> 4);
                uint32_t off = p * 512 + ((seg ^ (p & 7)) << 4);
                lda4(ah[mi], sb + SM_AHI + off);
                lda4(al[mi], sb + SM_ALO + off);
            }
#pragma unroll
            for (int j = 0; j < 8; j++) {
                int i = lane & 15;
                int brow = wn * 64 + j * 8 + (i & 7);
                uint32_t baddr = bb + brow * 80 + ((i >> 3) << 4);
                uint32_t bh[2], bl[2];
                ldb2(bh, baddr);
                ldb2(bl, baddr + 32);
#pragma unroll
                for (int mi = 0; mi < 2; mi++) {
                    mma16816(acc[mi][j], ah[mi], bh);
                    mma16816(acc[mi][j], al[mi], bh);
                    mma16816(acc[mi][j], ah[mi], bl);
                }
            }
        }

        // fold N-tile into running per-row top-2 (ascending c -> first-min tiebreak)
#pragma unroll
        for (int j = 0; j < 8; j++) {
            int cbase = nt * 128 + wn * 64 + j * 8 + (lane & 3) * 2;
#pragma unroll
            for (int mi = 0; mi < 2; mi++)
#pragma unroll
                for (int rh = 0; rh < 2; rh++) {
                    int r = mi * 2 + rh;
#pragma unroll
                    for (int cc = 0; cc < 2; cc++) {
                        float v = acc[mi][j][rh * 2 + cc];
                        int c = cbase + cc;
                        if (v > tb[r]) { t2[r] = tb[r]; tb[r] = v; ti[r] = c; }
                        else if (v > t2[r]) t2[r] = v;
                    }
                }
        }
    }

    // quad merge (4 lanes share each row)
#pragma unroll
    for (int k = 1; k <= 2; k <<= 1) {
#pragma unroll
        for (int r = 0; r < 4; r++) {
            float ob = __shfl_xor_sync(0xffffffffu, tb[r], k);
            float o2 = __shfl_xor_sync(0xffffffffu, t2[r], k);
            int   oi = __shfl_xor_sync(0xffffffffu, ti[r], k);
            if (ob > tb[r] || (ob == tb[r] && oi < ti[r])) {
                t2[r] = fmaxf(tb[r], o2); tb[r] = ob; ti[r] = oi;
            } else {
                t2[r] = fmaxf(t2[r], ob);
            }
        }
    }

    __syncthreads();                         // B ring dead; reuse as reduce scratch
    float* rv  = (float*)(smem + SM_RED);
    float* r2v = rv + 256;
    int*   rix = (int*)(r2v + 256);
    if ((lane & 3) == 0) {
#pragma unroll
        for (int r = 0; r < 4; r++) {
            int row = wm * 32 + (r >> 1) * 16 + (r & 1) * 8 + (lane >> 2);
            rv[row * 2 + wn]  = tb[r];
            r2v[row * 2 + wn] = t2[r];
            rix[row * 2 + wn] = ti[r];
        }
    }
    __syncthreads();
    if (tid < 128) {
        float b0 = rv[tid * 2],  b1 = rv[tid * 2 + 1];
        float s0 = r2v[tid * 2], s1 = r2v[tid * 2 + 1];
        int   i0 = rix[tid * 2], i1 = rix[tid * 2 + 1];
        float bb_, ss_;
        int   ii_;
        if (b1 > b0 || (b1 == b0 && i1 < i0)) { bb_ = b1; ii_ = i1; ss_ = fmaxf(b0, s1); }
        else                                   { bb_ = b0; ii_ = i0; ss_ = fmaxf(s0, b1); }
        g_idx[lvl][m0 + tid] = ii_;
        if (bb_ - ss_ < TAU_S) {
            int pos = atomicAdd(&g_refine_count[lvl], 1);
            g_refine_list[lvl][pos] = m0 + tid;
        }
    }
}

// ---------------- kernel: double-f32 exact refinement (1 point/block, 1 code/thread) ----------------
__global__ __launch_bounds__(1024)
void refine_kernel(const float* __restrict__ h_top, const float* __restrict__ h_bot) {
    int lvl = blockIdx.y;
    const float* h = lvl ? h_bot : h_top;
    const float* bt = g_bt + (size_t)lvl * DIM * KCODES;
    int cnt = g_refine_count[lvl];

    __shared__ float xs[DIM];
    __shared__ float rh[1024], rl[1024];
    __shared__ int   rix[1024];

    int tid = threadIdx.x;
    int c = tid;

    for (int e = blockIdx.x; e < cnt; e += gridDim.x) {
        int p = g_refine_list[lvl][e];
        int b = p / TLEN, t = p % TLEN;
        __syncthreads();
        if (tid < DIM)
            xs[tid] = h[((size_t)b * DIM + tid) * TLEN + t];
        __syncthreads();

        float hi = 0.f, lo = 0.f;
#pragma unroll 8
        for (int d = 0; d < DIM; d++) {
            float ev = bt[(size_t)d * KCODES + c];
            float x  = xs[d];
            float s  = x - ev;
            float bb = s - x;
            float err = (x - (s - bb)) + ((-ev) - bb);
            float pq = s * s;
            float pe = fmaf(s, s, -pq);
            float cross = fmaf(2.f * s, err, fmaf(err, err, pe));
            float t1  = hi + pq;
            float bb2 = t1 - hi;
            float e2  = (hi - (t1 - bb2)) + (pq - bb2);
            hi = t1;
            lo += e2 + cross;
        }
        float th = hi + lo;
        float tl = lo - (th - hi);

        rh[tid] = th; rl[tid] = tl; rix[tid] = c;
        __syncthreads();
#pragma unroll
        for (int s = 512; s; s >>= 1) {
            if (tid < s) {
                float oh = rh[tid + s], ol = rl[tid + s];
                int   oi = rix[tid + s];
                float mh = rh[tid], ml = rl[tid];
                int   mi = rix[tid];
                if (oh < mh || (oh == mh && (ol < ml || (ol == ml && oi < mi)))) {
                    rh[tid] = oh; rl[tid] = ol; rix[tid] = oi;
                }
            }
            __syncthreads();
        }
        if (tid == 0) g_idx[lvl][p] = rix[0];
    }
}

// ---------------- kernel: gather z_q + per-block loss partials ----------------
__global__ __launch_bounds__(256)
void gather_kernel(const float* __restrict__ h_top, const float* __restrict__ h_bot,
                   const float* __restrict__ cb_top, const float* __restrict__ cb_bot,
                   float* __restrict__ out) {
    int lvl = blockIdx.z;
    const float* h  = lvl ? h_bot  : h_top;
    const float* cb = lvl ? cb_bot : cb_top;
    float* z = out + (size_t)lvl * NELEM;

    int b = blockIdx.y;
    int t0 = blockIdx.x * 32;
    int tid = threadIdx.x;

    __shared__ int   sidx[32];
    __shared__ float sh[32 * 33];
    __shared__ float red[256];

    if (tid < 32) sidx[tid] = g_idx[lvl][b * TLEN + t0 + tid];
    __syncthreads();

    float lacc = 0.f;
    int j2 = tid >> 3, l8 = tid & 7;

    for (int dc = 0; dc < DIM; dc += 32) {
        float4 v = *(const float4*)(cb + (size_t)sidx[j2] * DIM + dc + l8 * 4);
        sh[(l8 * 4 + 0) * 33 + j2] = v.x;
        sh[(l8 * 4 + 1) * 33 + j2] = v.y;
        sh[(l8 * 4 + 2) * 33 + j2] = v.z;
        sh[(l8 * 4 + 3) * 33 + j2] = v.w;
        __syncthreads();
#pragma unroll
        for (int it = 0; it < 4; it++) {
            int i = tid + it * 256;
            int dl = i >> 5, j = i & 31;
            size_t off = ((size_t)b * DIM + dc + dl) * TLEN + t0 + j;
            float zz = sh[dl * 33 + j];
            z[off] = zz;
            float e = h[off] - zz;
            lacc = fmaf(e, e, lacc);
        }
        __syncthreads();
    }

    red[tid] = lacc;
    __syncthreads();
#pragma unroll
    for (int s = 128; s; s >>= 1) {
        if (tid < s) red[tid] += red[tid + s];
        __syncthreads();
    }
    if (tid == 0) g_partial[lvl][blockIdx.y * (TLEN / 32) + blockIdx.x] = red[0];
}

// ---------------- kernel: finalize scalars ----------------
__global__ __launch_bounds__(1024)
void finalize_kernel(float* __restrict__ out) {
    __shared__ int   hist[KCODES];
    __shared__ float red[1024];
    int tid = threadIdx.x;

    float sums[2];
#pragma unroll
    for (int lvl = 0; lvl < 2; lvl++) {
        red[tid] = g_partial[lvl][tid];
        __syncthreads();
        for (int s = 512; s; s >>= 1) {
            if (tid < s) red[tid] += red[tid + s];
            __syncthreads();
        }
        sums[lvl] = red[0];
        __syncthreads();
    }
    float loss = sums[0] * (1.f / (float)NELEM) + sums[1] * (1.f / (float)NELEM);

    float ppl[2];
#pragma unroll
    for (int lvl = 0; lvl < 2; lvl++) {
        hist[tid] = 0;
        __syncthreads();
#pragma unroll
        for (int i = 0; i < NPTS / 1024; i++)
            atomicAdd(&hist[g_idx[lvl][i * 1024 + tid]], 1);
        __syncthreads();
        float p = (float)hist[tid] * (1.f / (float)NPTS);
        red[tid] = p * logf(p + 1e-10f);
        __syncthreads();
        for (int s = 512; s; s >>= 1) {
            if (tid < s) red[tid] += red[tid + s];
            __syncthreads();
        }
        ppl[lvl] = expf(-red[0]);
        __syncthreads();
    }

    if (tid == 0) {
        size_t base = (size_t)2 * NELEM;
        out[base + 0] = loss;
        out[base + 1] = loss;
        out[base + 2] = ppl[0];
        out[base + 3] = ppl[1];
    }
}

// ---------------- launcher ----------------
extern "C" void kernel_launch(void* const* d_in, const int* in_sizes, int n_in,
                              void* d_out, int out_size) {
    const float* h_top  = (const float*)d_in[0];
    const float* h_bot  = (const float*)d_in[1];
    const float* cb_top = (const float*)d_in[2];
    const float* cb_bot = (const float*)d_in[3];
    float* out = (float*)d_out;

    cudaFuncSetAttribute(argmin_kernel,
                         cudaFuncAttributeMaxDynamicSharedMemorySize, ARG_SMEM);

    xsplit_kernel<<<dim3(TLEN / 32, DIM / 64, BATCH * LEVELS), 256>>>(h_top, h_bot);
    ecnorm_kernel<<<dim3(KCODES / 8, LEVELS), 256>>>(cb_top, cb_bot);
    btrans_kernel<<<dim3(KCODES / 32, DIM / 32, LEVELS), 256>>>(cb_top, cb_bot);
    argmin_kernel<<<dim3(NPTS / 128, LEVELS), 256, ARG_SMEM>>>();
    refine_kernel<<<dim3(512, LEVELS), 1024>>>(h_top, h_bot);
    gather_kernel<<<dim3(TLEN / 32, BATCH, LEVELS), 256>>>(h_top, h_bot, cb_top, cb_bot, out);
    finalize_kernel<<<1, 1024>>>(out);
}

// round 10
// speedup vs baseline: 3.0160x; 1.1338x over previous
#include <cuda_runtime.h>
#include <cuda_bf16.h>
#include <cstdint>
#include <cfloat>

#define LEVELS 2
#define BATCH  16
#define DIM    256
#define TLEN   2048
#define NPTS   (BATCH * TLEN)       // 32768 points per level
#define KCODES 1024
#define NELEM  (BATCH * DIM * TLEN) // 8388608 per level
#define GATHER_BLOCKS (BATCH * (TLEN / 32))
#define TAU_S  0.004f               // ~11 sigma of split-bf16 HMMA error in s-space

// ---------------- scratch (no allocations allowed) ----------------
__device__ float    g_bt[(size_t)LEVELS * DIM * KCODES];   // codebook transposed (refine)
__device__ float2   g_cninit[LEVELS * (KCODES / 2)];       // packed (-cn/2) pairs
__device__ float    g_partial[LEVELS][GATHER_BLOCKS];
__device__ int      g_idx[LEVELS][NPTS];
__device__ int      g_refine_count[LEVELS];
__device__ int      g_refine_list[LEVELS][NPTS];
// bf16 splits packed as u32 pairs (elem 2d in low half): [p][d] and [c][d]
__device__ unsigned g_xhi[(size_t)LEVELS * NPTS * (DIM / 2)];
__device__ unsigned g_xlo[(size_t)LEVELS * NPTS * (DIM / 2)];
__device__ unsigned g_ehi[(size_t)LEVELS * KCODES * (DIM / 2)];
__device__ unsigned g_elo[(size_t)LEVELS * KCODES * (DIM / 2)];

// ---------------- helpers ----------------
__device__ __forceinline__ void cp16(void* dst, const void* src) {
    unsigned s = (unsigned)__cvta_generic_to_shared(dst);
    asm volatile("cp.async.cg.shared.global [%0], [%1], 16;" :: "r"(s), "l"(src) : "memory");
}
#define CP_COMMIT() asm volatile("cp.async.commit_group;" ::: "memory")
#define CP_WAIT1()  asm volatile("cp.async.wait_group 1;" ::: "memory")
#define CP_WAIT0()  asm volatile("cp.async.wait_group 0;" ::: "memory")

__device__ __forceinline__ void lda4(uint32_t r[4], uint32_t addr) {
    asm volatile("ldmatrix.sync.aligned.m8n8.x4.shared.b16 {%0,%1,%2,%3}, [%4];"
                 : "=r"(r[0]), "=r"(r[1]), "=r"(r[2]), "=r"(r[3]) : "r"(addr));
}
// B tile smem is [n][k] (row=code, col=dim) -> NON-trans ldmatrix delivers the
// mma B fragment directly (lane l: B_smem[n=l/4][k=2*(l%4)+{0,1}]).
__device__ __forceinline__ void ldb2(uint32_t r[2], uint32_t addr) {
    asm volatile("ldmatrix.sync.aligned.m8n8.x2.shared.b16 {%0,%1}, [%2];"
                 : "=r"(r[0]), "=r"(r[1]) : "r"(addr));
}
__device__ __forceinline__ void mma16816(float d[4], const uint32_t a[4], const uint32_t b[2]) {
    asm volatile("mma.sync.aligned.m16n8k16.row.col.f32.bf16.bf16.f32 "
                 "{%0,%1,%2,%3}, {%4,%5,%6,%7}, {%8,%9}, {%0,%1,%2,%3};"
                 : "+f"(d[0]), "+f"(d[1]), "+f"(d[2]), "+f"(d[3])
                 : "r"(a[0]), "r"(a[1]), "r"(a[2]), "r"(a[3]), "r"(b[0]), "r"(b[1]));
}

// ---------------- kernel: split+transpose h -> x_hi/x_lo bf16 [lvl][p][d] ----------------
__global__ __launch_bounds__(256)
void xsplit_kernel(const float* __restrict__ h_top, const float* __restrict__ h_bot) {
    __shared__ float s[32][65];
    int z = blockIdx.z, lvl = z >> 4, b = z & 15;
    const float* h = lvl ? h_bot : h_top;
    int t0 = blockIdx.x * 32, d0 = blockIdx.y * 64;
    int tid = threadIdx.x, lane = tid & 31, w = tid >> 5;
#pragma unroll
    for (int k = 0; k < 8; k++) {
        int dl = w + 8 * k;
        s[lane][dl] = h[((size_t)b * DIM + d0 + dl) * TLEN + t0 + lane];
    }
    __syncthreads();
    int pl = tid >> 3, q = tid & 7;
    int p = b * TLEN + t0 + pl;
    size_t rowbase = ((size_t)lvl * NPTS + p) * (DIM / 2) + (d0 >> 1);
#pragma unroll
    for (int k = 0; k < 4; k++) {
        int d2 = q + 8 * k;
        float v0 = s[pl][2 * d2], v1 = s[pl][2 * d2 + 1];
        __nv_bfloat16 h0 = __float2bfloat16(v0), h1 = __float2bfloat16(v1);
        __nv_bfloat16 l0 = __float2bfloat16(v0 - __bfloat162float(h0));
        __nv_bfloat16 l1 = __float2bfloat16(v1 - __bfloat162float(h1));
        g_xhi[rowbase + d2] = ((unsigned)__bfloat16_as_ushort(h1) << 16) | __bfloat16_as_ushort(h0);
        g_xlo[rowbase + d2] = ((unsigned)__bfloat16_as_ushort(l1) << 16) | __bfloat16_as_ushort(l0);
    }
}

// ---------------- kernel: codebook split + (-cn/2) + counter reset ----------------
__global__ __launch_bounds__(256)
void ecnorm_kernel(const float* __restrict__ cb_top, const float* __restrict__ cb_bot) {
    __shared__ float s8[8];
    int lvl = blockIdx.y;
    if (blockIdx.x == 0 && threadIdx.x == 0) g_refine_count[lvl] = 0;
    const float* cb = lvl ? cb_bot : cb_top;
    int w = threadIdx.x >> 5, lane = threadIdx.x & 31;
    int c = blockIdx.x * 8 + w;
    const float* row = cb + (size_t)c * DIM;
    size_t rowbase = ((size_t)lvl * KCODES + c) * (DIM / 2);
    float sacc = 0.f;
#pragma unroll
    for (int k = 0; k < 4; k++) {
        int d2 = lane + 32 * k;
        float v0 = row[2 * d2], v1 = row[2 * d2 + 1];
        sacc = fmaf(v0, v0, sacc);
        sacc = fmaf(v1, v1, sacc);
        __nv_bfloat16 h0 = __float2bfloat16(v0), h1 = __float2bfloat16(v1);
        __nv_bfloat16 l0 = __float2bfloat16(v0 - __bfloat162float(h0));
        __nv_bfloat16 l1 = __float2bfloat16(v1 - __bfloat162float(h1));
        g_ehi[rowbase + d2] = ((unsigned)__bfloat16_as_ushort(h1) << 16) | __bfloat16_as_ushort(h0);
        g_elo[rowbase + d2] = ((unsigned)__bfloat16_as_ushort(l1) << 16) | __bfloat16_as_ushort(l0);
    }
#pragma unroll
    for (int o = 16; o; o >>= 1) sacc += __shfl_down_sync(0xffffffffu, sacc, o);
    if (lane == 0) s8[w] = sacc;
    __syncthreads();
    if (threadIdx.x < 4)
        g_cninit[lvl * (KCODES / 2) + blockIdx.x * 4 + threadIdx.x] =
            make_float2(-0.5f * s8[2 * threadIdx.x], -0.5f * s8[2 * threadIdx.x + 1]);
}

// ---------------- kernel: transpose codebook to [d][c] (refine uses it) ----------------
__global__ __launch_bounds__(256)
void btrans_kernel(const float* __restrict__ cb_top, const float* __restrict__ cb_bot) {
    __shared__ float s[32][33];
    int lvl = blockIdx.z;
    const float* cb = lvl ? cb_bot : cb_top;
    int c0 = blockIdx.x * 32, d0 = blockIdx.y * 32;
    int lx = threadIdx.x & 31, ly = threadIdx.x >> 5;
#pragma unroll
    for (int k = 0; k < 4; k++)
        s[ly + 8 * k][lx] = cb[(size_t)(c0 + ly + 8 * k) * DIM + d0 + lx];
    __syncthreads();
#pragma unroll
    for (int k = 0; k < 4; k++)
        g_bt[((size_t)lvl * DIM + d0 + ly + 8 * k) * KCODES + c0 + lx] = s[lx][ly + 8 * k];
}

// ---------------- argmin GEMM via mma.sync bf16 (split-f32), M=64 tile, 2 CTAs/SM ----------------
// smem: A_hi 32KB | A_lo 32KB | B ring 3 x 10KB (rows padded to 80B)  => 94KB/CTA
#define SM_AHI 0
#define SM_ALO 32768
#define SM_B   65536
#define SM_RED 65536             // reduce scratch reuses B ring after mainloop
#define ARG_SMEM (65536 + 3 * 10240)

__device__ __forceinline__ void issueB(char* smem, int s, int tid, size_t L) {
    int nt = s >> 4, ch = s & 15, buf = s % 3;
    int row = tid >> 1, sg = tid & 1;
    char* bb = smem + SM_B + buf * 10240;
    size_t src = (L + nt * 128 + row) * (size_t)128 + ch * 8 + sg * 4;
    cp16(bb + row * 80 + sg * 16,      &g_ehi[src]);
    cp16(bb + row * 80 + 32 + sg * 16, &g_elo[src]);
    CP_COMMIT();
}

__global__ __launch_bounds__(256, 2)
void argmin_kernel() {
    extern __shared__ __align__(128) char smem[];
    int tid = threadIdx.x, lane = tid & 31, wid = tid >> 5;
    int wm = wid >> 1, wn = wid & 1;           // 4 warp-rows x 2 warp-cols
    int lvl = blockIdx.y;
    int m0 = blockIdx.x * 64;
    size_t XL = (size_t)lvl * NPTS;
    size_t EL = (size_t)lvl * KCODES;
    uint32_t sb = (uint32_t)__cvta_generic_to_shared(smem);

    // ---- prologue: A (hi+lo, 64 rows) into swizzled resident smem, then B chunk 0 ----
#pragma unroll
    for (int i = 0; i < 8; i++) {
        int idx = tid + i * 256;            // 2048 segs per part
        int row = idx >> 5, seg = idx & 31;
        int soff = ((seg ^ (row & 7)) << 4);
        size_t src = (XL + m0 + row) * (size_t)128 + seg * 4;
        cp16(smem + SM_AHI + row * 512 + soff, &g_xhi[src]);
        cp16(smem + SM_ALO + row * 512 + soff, &g_xlo[src]);
    }
    CP_COMMIT();
    issueB(smem, 0, tid, EL);

    float tb[2], t2[2];
    int   ti[2];
#pragma unroll
    for (int r = 0; r < 2; r++) { tb[r] = -FLT_MAX; t2[r] = -FLT_MAX; ti[r] = 0; }

#pragma unroll 1
    for (int nt = 0; nt < 8; nt++) {
        // init accumulators with -cn/2 (per-column)
        float acc[8][4];
#pragma unroll
        for (int j = 0; j < 8; j++) {
            int c0 = nt * 128 + wn * 64 + j * 8 + (lane & 3) * 2;
            float2 ci = g_cninit[lvl * (KCODES / 2) + (c0 >> 1)];
            acc[j][0] = ci.x; acc[j][1] = ci.y;
            acc[j][2] = ci.x; acc[j][3] = ci.y;
        }

#pragma unroll 1
        for (int ch = 0; ch < 16; ch++) {
            int s = nt * 16 + ch;
            if (s < 127) { issueB(smem, s + 1, tid, EL); CP_WAIT1(); }
            else         { CP_WAIT0(); }
            __syncthreads();
            uint32_t bb = sb + SM_B + (s % 3) * 10240;

            // ldmatrix A fragments (1 m-tile of 16 rows, hi + lo)
            uint32_t ah[4], al[4];
            {
                int p = wm * 16 + (lane & 7) + ((lane >> 3) & 1) * 8;
                int seg = ch * 2 + (lane >> 4);
                uint32_t off = p * 512 + ((seg ^ (p & 7)) << 4);
                lda4(ah, sb + SM_AHI + off);
                lda4(al, sb + SM_ALO + off);
            }
#pragma unroll
            for (int j = 0; j < 8; j++) {
                int i = lane & 15;
                int brow = wn * 64 + j * 8 + (i & 7);
                uint32_t baddr = bb + brow * 80 + ((i >> 3) << 4);
                uint32_t bh[2], bl[2];
                ldb2(bh, baddr);
                ldb2(bl, baddr + 32);
                mma16816(acc[j], ah, bh);
                mma16816(acc[j], al, bh);
                mma16816(acc[j], ah, bl);
            }
        }

        // fold N-tile into running per-row top-2 (ascending c -> first-min tiebreak)
#pragma unroll
        for (int j = 0; j < 8; j++) {
            int cbase = nt * 128 + wn * 64 + j * 8 + (lane & 3) * 2;
#pragma unroll
            for (int rh = 0; rh < 2; rh++) {
#pragma unroll
                for (int cc = 0; cc < 2; cc++) {
                    float v = acc[j][rh * 2 + cc];
                    int c = cbase + cc;
                    if (v > tb[rh]) { t2[rh] = tb[rh]; tb[rh] = v; ti[rh] = c; }
                    else if (v > t2[rh]) t2[rh] = v;
                }
            }
        }
    }

    // quad merge (4 lanes share each row)
#pragma unroll
    for (int k = 1; k <= 2; k <<= 1) {
#pragma unroll
        for (int r = 0; r < 2; r++) {
            float ob = __shfl_xor_sync(0xffffffffu, tb[r], k);
            float o2 = __shfl_xor_sync(0xffffffffu, t2[r], k);
            int   oi = __shfl_xor_sync(0xffffffffu, ti[r], k);
            if (ob > tb[r] || (ob == tb[r] && oi < ti[r])) {
                t2[r] = fmaxf(tb[r], o2); tb[r] = ob; ti[r] = oi;
            } else {
                t2[r] = fmaxf(t2[r], ob);
            }
        }
    }

    __syncthreads();                         // B ring dead; reuse as reduce scratch
    float* rv  = (float*)(smem + SM_RED);
    float* r2v = rv + 128;
    int*   rix = (int*)(r2v + 128);
    if ((lane & 3) == 0) {
#pragma unroll
        for (int r = 0; r < 2; r++) {
            int row = wm * 16 + r * 8 + (lane >> 2);
            rv[row * 2 + wn]  = tb[r];
            r2v[row * 2 + wn] = t2[r];
            rix[row * 2 + wn] = ti[r];
        }
    }
    __syncthreads();
    if (tid < 64) {
        float b0 = rv[tid * 2],  b1 = rv[tid * 2 + 1];
        float s0 = r2v[tid * 2], s1 = r2v[tid * 2 + 1];
        int   i0 = rix[tid * 2], i1 = rix[tid * 2 + 1];
        float bb_, ss_;
        int   ii_;
        if (b1 > b0 || (b1 == b0 && i1 < i0)) { bb_ = b1; ii_ = i1; ss_ = fmaxf(b0, s1); }
        else                                   { bb_ = b0; ii_ = i0; ss_ = fmaxf(s0, b1); }
        g_idx[lvl][m0 + tid] = ii_;
        if (bb_ - ss_ < TAU_S) {
            int pos = atomicAdd(&g_refine_count[lvl], 1);
            g_refine_list[lvl][pos] = m0 + tid;
        }
    }
}

// ---------------- kernel: double-f32 exact refinement (1 point/block, 1 code/thread) ----------------
__global__ __launch_bounds__(1024)
void refine_kernel(const float* __restrict__ h_top, const float* __restrict__ h_bot) {
    int lvl = blockIdx.y;
    const float* h = lvl ? h_bot : h_top;
    const float* bt = g_bt + (size_t)lvl * DIM * KCODES;
    int cnt = g_refine_count[lvl];

    __shared__ float xs[DIM];
    __shared__ float rh[1024], rl[1024];
    __shared__ int   rix[1024];

    int tid = threadIdx.x;
    int c = tid;

    for (int e = blockIdx.x; e < cnt; e += gridDim.x) {
        int p = g_refine_list[lvl][e];
        int b = p / TLEN, t = p % TLEN;
        __syncthreads();
        if (tid < DIM)
            xs[tid] = h[((size_t)b * DIM + tid) * TLEN + t];
        __syncthreads();

        float hi = 0.f, lo = 0.f;
#pragma unroll 8
        for (int d = 0; d < DIM; d++) {
            float ev = bt[(size_t)d * KCODES + c];
            float x  = xs[d];
            float s  = x - ev;
            float bb = s - x;
            float err = (x - (s - bb)) + ((-ev) - bb);
            float pq = s * s;
            float pe = fmaf(s, s, -pq);
            float cross = fmaf(2.f * s, err, fmaf(err, err, pe));
            float t1  = hi + pq;
            float bb2 = t1 - hi;
            float e2  = (hi - (t1 - bb2)) + (pq - bb2);
            hi = t1;
            lo += e2 + cross;
        }
        float th = hi + lo;
        float tl = lo - (th - hi);

        rh[tid] = th; rl[tid] = tl; rix[tid] = c;
        __syncthreads();
#pragma unroll
        for (int s = 512; s; s >>= 1) {
            if (tid < s) {
                float oh = rh[tid + s], ol = rl[tid + s];
                int   oi = rix[tid + s];
                float mh = rh[tid], ml = rl[tid];
                int   mi = rix[tid];
                if (oh < mh || (oh == mh && (ol < ml || (ol == ml && oi < mi)))) {
                    rh[tid] = oh; rl[tid] = ol; rix[tid] = oi;
                }
            }
            __syncthreads();
        }
        if (tid == 0) g_idx[lvl][p] = rix[0];
    }
}

// ---------------- kernel: gather z_q + per-block loss partials ----------------
__global__ __launch_bounds__(256)
void gather_kernel(const float* __restrict__ h_top, const float* __restrict__ h_bot,
                   const float* __restrict__ cb_top, const float* __restrict__ cb_bot,
                   float* __restrict__ out) {
    int lvl = blockIdx.z;
    const float* h  = lvl ? h_bot  : h_top;
    const float* cb = lvl ? cb_bot : cb_top;
    float* z = out + (size_t)lvl * NELEM;

    int b = blockIdx.y;
    int t0 = blockIdx.x * 32;
    int tid = threadIdx.x;

    __shared__ int   sidx[32];
    __shared__ float sh[32 * 33];
    __shared__ float red[256];

    if (tid < 32) sidx[tid] = g_idx[lvl][b * TLEN + t0 + tid];
    __syncthreads();

    float lacc = 0.f;
    int j2 = tid >> 3, l8 = tid & 7;

    for (int dc = 0; dc < DIM; dc += 32) {
        float4 v = *(const float4*)(cb + (size_t)sidx[j2] * DIM + dc + l8 * 4);
        sh[(l8 * 4 + 0) * 33 + j2] = v.x;
        sh[(l8 * 4 + 1) * 33 + j2] = v.y;
        sh[(l8 * 4 + 2) * 33 + j2] = v.z;
        sh[(l8 * 4 + 3) * 33 + j2] = v.w;
        __syncthreads();
#pragma unroll
        for (int it = 0; it < 4; it++) {
            int i = tid + it * 256;
            int dl = i >> 5, j = i & 31;
            size_t off = ((size_t)b * DIM + dc + dl) * TLEN + t0 + j;
            float zz = sh[dl * 33 + j];
            z[off] = zz;
            float e = h[off] - zz;
            lacc = fmaf(e, e, lacc);
        }
        __syncthreads();
    }

    red[tid] = lacc;
    __syncthreads();
#pragma unroll
    for (int s = 128; s; s >>= 1) {
        if (tid < s) red[tid] += red[tid + s];
        __syncthreads();
    }
    if (tid == 0) g_partial[lvl][blockIdx.y * (TLEN / 32) + blockIdx.x] = red[0];
}

// ---------------- kernel: finalize scalars ----------------
__global__ __launch_bounds__(1024)
void finalize_kernel(float* __restrict__ out) {
    __shared__ int   hist[KCODES];
    __shared__ float red[1024];
    int tid = threadIdx.x;

    float sums[2];
#pragma unroll
    for (int lvl = 0; lvl < 2; lvl++) {
        red[tid] = g_partial[lvl][tid];
        __syncthreads();
        for (int s = 512; s; s >>= 1) {
            if (tid < s) red[tid] += red[tid + s];
            __syncthreads();
        }
        sums[lvl] = red[0];
        __syncthreads();
    }
    float loss = sums[0] * (1.f / (float)NELEM) + sums[1] * (1.f / (float)NELEM);

    float ppl[2];
#pragma unroll
    for (int lvl = 0; lvl < 2; lvl++) {
        hist[tid] = 0;
        __syncthreads();
#pragma unroll
        for (int i = 0; i < NPTS / 1024; i++)
            atomicAdd(&hist[g_idx[lvl][i * 1024 + tid]], 1);
        __syncthreads();
        float p = (float)hist[tid] * (1.f / (float)NPTS);
        red[tid] = p * logf(p + 1e-10f);
        __syncthreads();
        for (int s = 512; s; s >>= 1) {
            if (tid < s) red[tid] += red[tid + s];
            __syncthreads();
        }
        ppl[lvl] = expf(-red[0]);
        __syncthreads();
    }

    if (tid == 0) {
        size_t base = (size_t)2 * NELEM;
        out[base + 0] = loss;
        out[base + 1] = loss;
        out[base + 2] = ppl[0];
        out[base + 3] = ppl[1];
    }
}

// ---------------- launcher ----------------
extern "C" void kernel_launch(void* const* d_in, const int* in_sizes, int n_in,
                              void* d_out, int out_size) {
    const float* h_top  = (const float*)d_in[0];
    const float* h_bot  = (const float*)d_in[1];
    const float* cb_top = (const float*)d_in[2];
    const float* cb_bot = (const float*)d_in[3];
    float* out = (float*)d_out;

    cudaFuncSetAttribute(argmin_kernel,
                         cudaFuncAttributeMaxDynamicSharedMemorySize, ARG_SMEM);

    xsplit_kernel<<<dim3(TLEN / 32, DIM / 64, BATCH * LEVELS), 256>>>(h_top, h_bot);
    ecnorm_kernel<<<dim3(KCODES / 8, LEVELS), 256>>>(cb_top, cb_bot);
    btrans_kernel<<<dim3(KCODES / 32, DIM / 32, LEVELS), 256>>>(cb_top, cb_bot);
    argmin_kernel<<<dim3(NPTS / 64, LEVELS), 256, ARG_SMEM>>>();
    refine_kernel<<<dim3(512, LEVELS), 1024>>>(h_top, h_bot);
    gather_kernel<<<dim3(TLEN / 32, BATCH, LEVELS), 256>>>(h_top, h_bot, cb_top, cb_bot, out);
    finalize_kernel<<<1, 1024>>>(out);
}

// round 11
// speedup vs baseline: 3.2361x; 1.0730x over previous
#include <cuda_runtime.h>
#include <cuda_bf16.h>
#include <cstdint>
#include <cfloat>

#define LEVELS 2
#define BATCH  16
#define DIM    256
#define TLEN   2048
#define NPTS   (BATCH * TLEN)       // 32768 points per level
#define KCODES 1024
#define NELEM  (BATCH * DIM * TLEN) // 8388608 per level
#define GATHER_BLOCKS (BATCH * (TLEN / 32))
#define TAU_S  0.004f               // ~11 sigma of split-bf16 HMMA error in s-space

// ---------------- scratch (no allocations allowed) ----------------
__device__ float    g_bt[(size_t)LEVELS * DIM * KCODES];   // codebook transposed (refine)
__device__ float2   g_cninit[LEVELS * (KCODES / 2)];       // packed (-cn/2) pairs
__device__ float    g_partial[LEVELS][GATHER_BLOCKS];
__device__ int      g_idx[LEVELS][NPTS];
__device__ int      g_refine_count[LEVELS];
__device__ int      g_refine_list[LEVELS][NPTS];
// bf16 splits packed as u32 pairs (elem 2d in low half): [p][d] and [c][d]
__device__ unsigned g_xhi[(size_t)LEVELS * NPTS * (DIM / 2)];
__device__ unsigned g_xlo[(size_t)LEVELS * NPTS * (DIM / 2)];
__device__ unsigned g_ehi[(size_t)LEVELS * KCODES * (DIM / 2)];
__device__ unsigned g_elo[(size_t)LEVELS * KCODES * (DIM / 2)];

// ---------------- helpers ----------------
__device__ __forceinline__ void cp16(void* dst, const void* src) {
    unsigned s = (unsigned)__cvta_generic_to_shared(dst);
    asm volatile("cp.async.cg.shared.global [%0], [%1], 16;" :: "r"(s), "l"(src) : "memory");
}
#define CP_COMMIT() asm volatile("cp.async.commit_group;" ::: "memory")
#define CP_WAIT2()  asm volatile("cp.async.wait_group 2;" ::: "memory")
#define CP_WAIT0()  asm volatile("cp.async.wait_group 0;" ::: "memory")

__device__ __forceinline__ void lda4(uint32_t r[4], uint32_t addr) {
    asm volatile("ldmatrix.sync.aligned.m8n8.x4.shared.b16 {%0,%1,%2,%3}, [%4];"
                 : "=r"(r[0]), "=r"(r[1]), "=r"(r[2]), "=r"(r[3]) : "r"(addr));
}
__device__ __forceinline__ void mma16816(float d[4], const uint32_t a[4], const uint32_t b[2]) {
    asm volatile("mma.sync.aligned.m16n8k16.row.col.f32.bf16.bf16.f32 "
                 "{%0,%1,%2,%3}, {%4,%5,%6,%7}, {%8,%9}, {%0,%1,%2,%3};"
                 : "+f"(d[0]), "+f"(d[1]), "+f"(d[2]), "+f"(d[3])
                 : "r"(a[0]), "r"(a[1]), "r"(a[2]), "r"(a[3]), "r"(b[0]), "r"(b[1]));
}

// ---------------- kernel: split+transpose h -> x_hi/x_lo bf16 [lvl][p][d] ----------------
__global__ __launch_bounds__(256)
void xsplit_kernel(const float* __restrict__ h_top, const float* __restrict__ h_bot) {
    __shared__ float s[32][65];
    int z = blockIdx.z, lvl = z >> 4, b = z & 15;
    const float* h = lvl ? h_bot : h_top;
    int t0 = blockIdx.x * 32, d0 = blockIdx.y * 64;
    int tid = threadIdx.x, lane = tid & 31, w = tid >> 5;
#pragma unroll
    for (int k = 0; k < 8; k++) {
        int dl = w + 8 * k;
        s[lane][dl] = h[((size_t)b * DIM + d0 + dl) * TLEN + t0 + lane];
    }
    __syncthreads();
    int pl = tid >> 3, q = tid & 7;
    int p = b * TLEN + t0 + pl;
    size_t rowbase = ((size_t)lvl * NPTS + p) * (DIM / 2) + (d0 >> 1);
#pragma unroll
    for (int k = 0; k < 4; k++) {
        int d2 = q + 8 * k;
        float v0 = s[pl][2 * d2], v1 = s[pl][2 * d2 + 1];
        __nv_bfloat16 h0 = __float2bfloat16(v0), h1 = __float2bfloat16(v1);
        __nv_bfloat16 l0 = __float2bfloat16(v0 - __bfloat162float(h0));
        __nv_bfloat16 l1 = __float2bfloat16(v1 - __bfloat162float(h1));
        g_xhi[rowbase + d2] = ((unsigned)__bfloat16_as_ushort(h1) << 16) | __bfloat16_as_ushort(h0);
        g_xlo[rowbase + d2] = ((unsigned)__bfloat16_as_ushort(l1) << 16) | __bfloat16_as_ushort(l0);
    }
}

// ---------------- kernel: codebook split + (-cn/2) + counter reset ----------------
__global__ __launch_bounds__(256)
void ecnorm_kernel(const float* __restrict__ cb_top, const float* __restrict__ cb_bot) {
    __shared__ float s8[8];
    int lvl = blockIdx.y;
    if (blockIdx.x == 0 && threadIdx.x == 0) g_refine_count[lvl] = 0;
    const float* cb = lvl ? cb_bot : cb_top;
    int w = threadIdx.x >> 5, lane = threadIdx.x & 31;
    int c = blockIdx.x * 8 + w;
    const float* row = cb + (size_t)c * DIM;
    size_t rowbase = ((size_t)lvl * KCODES + c) * (DIM / 2);
    float sacc = 0.f;
#pragma unroll
    for (int k = 0; k < 4; k++) {
        int d2 = lane + 32 * k;
        float v0 = row[2 * d2], v1 = row[2 * d2 + 1];
        sacc = fmaf(v0, v0, sacc);
        sacc = fmaf(v1, v1, sacc);
        __nv_bfloat16 h0 = __float2bfloat16(v0), h1 = __float2bfloat16(v1);
        __nv_bfloat16 l0 = __float2bfloat16(v0 - __bfloat162float(h0));
        __nv_bfloat16 l1 = __float2bfloat16(v1 - __bfloat162float(h1));
        g_ehi[rowbase + d2] = ((unsigned)__bfloat16_as_ushort(h1) << 16) | __bfloat16_as_ushort(h0);
        g_elo[rowbase + d2] = ((unsigned)__bfloat16_as_ushort(l1) << 16) | __bfloat16_as_ushort(l0);
    }
#pragma unroll
    for (int o = 16; o; o >>= 1) sacc += __shfl_down_sync(0xffffffffu, sacc, o);
    if (lane == 0) s8[w] = sacc;
    __syncthreads();
    if (threadIdx.x < 4)
        g_cninit[lvl * (KCODES / 2) + blockIdx.x * 4 + threadIdx.x] =
            make_float2(-0.5f * s8[2 * threadIdx.x], -0.5f * s8[2 * threadIdx.x + 1]);
}

// ---------------- kernel: transpose codebook to [d][c] (refine uses it) ----------------
__global__ __launch_bounds__(256)
void btrans_kernel(const float* __restrict__ cb_top, const float* __restrict__ cb_bot) {
    __shared__ float s[32][33];
    int lvl = blockIdx.z;
    const float* cb = lvl ? cb_bot : cb_top;
    int c0 = blockIdx.x * 32, d0 = blockIdx.y * 32;
    int lx = threadIdx.x & 31, ly = threadIdx.x >> 5;
#pragma unroll
    for (int k = 0; k < 4; k++)
        s[ly + 8 * k][lx] = cb[(size_t)(c0 + ly + 8 * k) * DIM + d0 + lx];
    __syncthreads();
#pragma unroll
    for (int k = 0; k < 4; k++)
        g_bt[((size_t)lvl * DIM + d0 + ly + 8 * k) * KCODES + c0 + lx] = s[lx][ly + 8 * k];
}

// ---------------- argmin GEMM via mma.sync bf16 (split-f32), M=64, warp 32x32, 2 CTAs/SM ----------------
// smem: A_hi 32KB | A_lo 32KB | B ring 4 x 10KB (rows padded to 80B) => 104KB/CTA
#define SM_AHI 0
#define SM_ALO 32768
#define SM_B   65536
#define SM_RED 65536             // reduce scratch reuses B ring after mainloop
#define ARG_SMEM (65536 + 4 * 10240)

__device__ __forceinline__ void issueB(char* smem, int s, int tid, size_t L) {
    int nt = s >> 4, ch = s & 15, buf = s & 3;
    int row = tid >> 1, sg = tid & 1;
    char* bb = smem + SM_B + buf * 10240;
    size_t src = (L + nt * 128 + row) * (size_t)128 + ch * 8 + sg * 4;
    cp16(bb + row * 80 + sg * 16,      &g_ehi[src]);
    cp16(bb + row * 80 + 32 + sg * 16, &g_elo[src]);
    CP_COMMIT();
}

__global__ __launch_bounds__(256, 2)
void argmin_kernel() {
    extern __shared__ __align__(128) char smem[];
    int tid = threadIdx.x, lane = tid & 31, wid = tid >> 5;
    int wm = wid >> 2, wn = wid & 3;           // 2 warp-rows (32M) x 4 warp-cols (32N)
    int lvl = blockIdx.y;
    int m0 = blockIdx.x * 64;
    size_t XL = (size_t)lvl * NPTS;
    size_t EL = (size_t)lvl * KCODES;
    uint32_t sb = (uint32_t)__cvta_generic_to_shared(smem);

    // ---- prologue: A (hi+lo, 64 rows) resident swizzled smem; then B chunks 0..2 ----
#pragma unroll
    for (int i = 0; i < 8; i++) {
        int idx = tid + i * 256;            // 2048 segs per part
        int row = idx >> 5, seg = idx & 31;
        int soff = ((seg ^ (row & 7)) << 4);
        size_t src = (XL + m0 + row) * (size_t)128 + seg * 4;
        cp16(smem + SM_AHI + row * 512 + soff, &g_xhi[src]);
        cp16(smem + SM_ALO + row * 512 + soff, &g_xlo[src]);
    }
    CP_COMMIT();
    issueB(smem, 0, tid, EL);
    issueB(smem, 1, tid, EL);
    issueB(smem, 2, tid, EL);

    float tb[4], t2[4];
    int   ti[4];
#pragma unroll
    for (int r = 0; r < 4; r++) { tb[r] = -FLT_MAX; t2[r] = -FLT_MAX; ti[r] = 0; }

#pragma unroll 1
    for (int nt = 0; nt < 8; nt++) {
        // init accumulators with -cn/2 (per-column)
        float acc[2][4][4];
#pragma unroll
        for (int j = 0; j < 4; j++) {
            int c0 = nt * 128 + wn * 32 + j * 8 + (lane & 3) * 2;
            float2 ci = g_cninit[lvl * (KCODES / 2) + (c0 >> 1)];
#pragma unroll
            for (int mi = 0; mi < 2; mi++) {
                acc[mi][j][0] = ci.x; acc[mi][j][1] = ci.y;
                acc[mi][j][2] = ci.x; acc[mi][j][3] = ci.y;
            }
        }

#pragma unroll 1
        for (int ch = 0; ch < 16; ch++) {
            int s = nt * 16 + ch;
            if (s < 125) CP_WAIT2();      // groups s+1, s+2 pending; s complete
            else         CP_WAIT0();      // tail: drain (last 3 chunks)
            __syncthreads();
            if (s < 125) issueB(smem, s + 3, tid, EL);   // overwrites slot (s-1)&3, safe post-sync
            uint32_t bb = sb + SM_B + (s & 3) * 10240;

            // A fragments: 2 m-tiles (16 rows each), hi + lo
            uint32_t ah[2][4], al[2][4];
#pragma unroll
            for (int mi = 0; mi < 2; mi++) {
                int p = wm * 32 + mi * 16 + (lane & 7) + ((lane >> 3) & 1) * 8;
                int seg = ch * 2 + (lane >> 4);
                uint32_t off = p * 512 + ((seg ^ (p & 7)) << 4);
                lda4(ah[mi], sb + SM_AHI + off);
                lda4(al[mi], sb + SM_ALO + off);
            }

            // B fragments via x4: lane-group g -> matrix g = (n-tile jp+(g>>1), k-half g&1)
            uint32_t bh[8], bl[8];
            {
                int g = lane >> 3, i = lane & 7;
                uint32_t a0 = bb + (uint32_t)(wn * 32 + (g >> 1) * 8 + i) * 80 + (g & 1) * 16;
                lda4(&bh[0], a0);                 // n-tiles 0,1
                lda4(&bh[4], a0 + 16 * 80);       // n-tiles 2,3
                lda4(&bl[0], a0 + 32);
                lda4(&bl[4], a0 + 16 * 80 + 32);
            }
#pragma unroll
            for (int j = 0; j < 4; j++) {
#pragma unroll
                for (int mi = 0; mi < 2; mi++) {
                    mma16816(acc[mi][j], ah[mi], &bh[2 * j]);
                    mma16816(acc[mi][j], al[mi], &bh[2 * j]);
                    mma16816(acc[mi][j], ah[mi], &bl[2 * j]);
                }
            }
        }

        // fold N-tile into running per-row top-2 (ascending c -> first-min tiebreak)
#pragma unroll
        for (int j = 0; j < 4; j++) {
            int cbase = nt * 128 + wn * 32 + j * 8 + (lane & 3) * 2;
#pragma unroll
            for (int mi = 0; mi < 2; mi++)
#pragma unroll
                for (int rh = 0; rh < 2; rh++) {
                    int r = mi * 2 + rh;
#pragma unroll
                    for (int cc = 0; cc < 2; cc++) {
                        float v = acc[mi][j][rh * 2 + cc];
                        int c = cbase + cc;
                        if (v > tb[r]) { t2[r] = tb[r]; tb[r] = v; ti[r] = c; }
                        else if (v > t2[r]) t2[r] = v;
                    }
                }
        }
    }

    // quad merge (4 lanes share each row)
#pragma unroll
    for (int k = 1; k <= 2; k <<= 1) {
#pragma unroll
        for (int r = 0; r < 4; r++) {
            float ob = __shfl_xor_sync(0xffffffffu, tb[r], k);
            float o2 = __shfl_xor_sync(0xffffffffu, t2[r], k);
            int   oi = __shfl_xor_sync(0xffffffffu, ti[r], k);
            if (ob > tb[r] || (ob == tb[r] && oi < ti[r])) {
                t2[r] = fmaxf(tb[r], o2); tb[r] = ob; ti[r] = oi;
            } else {
                t2[r] = fmaxf(t2[r], ob);
            }
        }
    }

    __syncthreads();                         // B ring dead; reuse as reduce scratch
    float* rv  = (float*)(smem + SM_RED);    // 64 rows x 4 wn
    float* r2v = rv + 256;
    int*   rix = (int*)(r2v + 256);
    if ((lane & 3) == 0) {
#pragma unroll
        for (int r = 0; r < 4; r++) {
            int row = wm * 32 + (r >> 1) * 16 + (r & 1) * 8 + (lane >> 2);
            rv[row * 4 + wn]  = tb[r];
            r2v[row * 4 + wn] = t2[r];
            rix[row * 4 + wn] = ti[r];
        }
    }
    __syncthreads();
    if (tid < 64) {
        float bv = rv[tid * 4];
        float bs = r2v[tid * 4];
        int   bi = rix[tid * 4];
#pragma unroll
        for (int x = 1; x < 4; x++) {
            float v  = rv[tid * 4 + x];
            float v2 = r2v[tid * 4 + x];
            int   ii = rix[tid * 4 + x];
            if (v > bv || (v == bv && ii < bi)) { bs = fmaxf(bv, v2); bv = v; bi = ii; }
            else                                 bs = fmaxf(bs, v);
        }
        g_idx[lvl][m0 + tid] = bi;
        if (bv - bs < TAU_S) {
            int pos = atomicAdd(&g_refine_count[lvl], 1);
            g_refine_list[lvl][pos] = m0 + tid;
        }
    }
}

// ---------------- kernel: double-f32 exact refinement (1 point/block, 1 code/thread) ----------------
__global__ __launch_bounds__(1024)
void refine_kernel(const float* __restrict__ h_top, const float* __restrict__ h_bot) {
    int lvl = blockIdx.y;
    const float* h = lvl ? h_bot : h_top;
    const float* bt = g_bt + (size_t)lvl * DIM * KCODES;
    int cnt = g_refine_count[lvl];

    __shared__ float xs[DIM];
    __shared__ float rh[1024], rl[1024];
    __shared__ int   rix[1024];

    int tid = threadIdx.x;
    int c = tid;

    for (int e = blockIdx.x; e < cnt; e += gridDim.x) {
        int p = g_refine_list[lvl][e];
        int b = p / TLEN, t = p % TLEN;
        __syncthreads();
        if (tid < DIM)
            xs[tid] = h[((size_t)b * DIM + tid) * TLEN + t];
        __syncthreads();

        float hi = 0.f, lo = 0.f;
#pragma unroll 8
        for (int d = 0; d < DIM; d++) {
            float ev = bt[(size_t)d * KCODES + c];
            float x  = xs[d];
            float s  = x - ev;
            float bb = s - x;
            float err = (x - (s - bb)) + ((-ev) - bb);
            float pq = s * s;
            float pe = fmaf(s, s, -pq);
            float cross = fmaf(2.f * s, err, fmaf(err, err, pe));
            float t1  = hi + pq;
            float bb2 = t1 - hi;
            float e2  = (hi - (t1 - bb2)) + (pq - bb2);
            hi = t1;
            lo += e2 + cross;
        }
        float th = hi + lo;
        float tl = lo - (th - hi);

        rh[tid] = th; rl[tid] = tl; rix[tid] = c;
        __syncthreads();
#pragma unroll
        for (int s = 512; s; s >>= 1) {
            if (tid < s) {
                float oh = rh[tid + s], ol = rl[tid + s];
                int   oi = rix[tid + s];
                float mh = rh[tid], ml = rl[tid];
                int   mi = rix[tid];
                if (oh < mh || (oh == mh && (ol < ml || (ol == ml && oi < mi)))) {
                    rh[tid] = oh; rl[tid] = ol; rix[tid] = oi;
                }
            }
            __syncthreads();
        }
        if (tid == 0) g_idx[lvl][p] = rix[0];
    }
}

// ---------------- kernel: gather z_q + per-block loss partials ----------------
__global__ __launch_bounds__(256)
void gather_kernel(const float* __restrict__ h_top, const float* __restrict__ h_bot,
                   const float* __restrict__ cb_top, const float* __restrict__ cb_bot,
                   float* __restrict__ out) {
    int lvl = blockIdx.z;
    const float* h  = lvl ? h_bot  : h_top;
    const float* cb = lvl ? cb_bot : cb_top;
    float* z = out + (size_t)lvl * NELEM;

    int b = blockIdx.y;
    int t0 = blockIdx.x * 32;
    int tid = threadIdx.x;

    __shared__ int   sidx[32];
    __shared__ float sh[32 * 33];
    __shared__ float red[256];

    if (tid < 32) sidx[tid] = g_idx[lvl][b * TLEN + t0 + tid];
    __syncthreads();

    float lacc = 0.f;
    int j2 = tid >> 3, l8 = tid & 7;

    for (int dc = 0; dc < DIM; dc += 32) {
        float4 v = *(const float4*)(cb + (size_t)sidx[j2] * DIM + dc + l8 * 4);
        sh[(l8 * 4 + 0) * 33 + j2] = v.x;
        sh[(l8 * 4 + 1) * 33 + j2] = v.y;
        sh[(l8 * 4 + 2) * 33 + j2] = v.z;
        sh[(l8 * 4 + 3) * 33 + j2] = v.w;
        __syncthreads();
#pragma unroll
        for (int it = 0; it < 4; it++) {
            int i = tid + it * 256;
            int dl = i >> 5, j = i & 31;
            size_t off = ((size_t)b * DIM + dc + dl) * TLEN + t0 + j;
            float zz = sh[dl * 33 + j];
            z[off] = zz;
            float e = h[off] - zz;
            lacc = fmaf(e, e, lacc);
        }
        __syncthreads();
    }

    red[tid] = lacc;
    __syncthreads();
#pragma unroll
    for (int s = 128; s; s >>= 1) {
        if (tid < s) red[tid] += red[tid + s];
        __syncthreads();
    }
    if (tid == 0) g_partial[lvl][blockIdx.y * (TLEN / 32) + blockIdx.x] = red[0];
}

// ---------------- kernel: finalize scalars ----------------
__global__ __launch_bounds__(1024)
void finalize_kernel(float* __restrict__ out) {
    __shared__ int   hist[KCODES];
    __shared__ float red[1024];
    int tid = threadIdx.x;

    float sums[2];
#pragma unroll
    for (int lvl = 0; lvl < 2; lvl++) {
        red[tid] = g_partial[lvl][tid];
        __syncthreads();
        for (int s = 512; s; s >>= 1) {
            if (tid < s) red[tid] += red[tid + s];
            __syncthreads();
        }
        sums[lvl] = red[0];
        __syncthreads();
    }
    float loss = sums[0] * (1.f / (float)NELEM) + sums[1] * (1.f / (float)NELEM);

    float ppl[2];
#pragma unroll
    for (int lvl = 0; lvl < 2; lvl++) {
        hist[tid] = 0;
        __syncthreads();
#pragma unroll
        for (int i = 0; i < NPTS / 1024; i++)
            atomicAdd(&hist[g_idx[lvl][i * 1024 + tid]], 1);
        __syncthreads();
        float p = (float)hist[tid] * (1.f / (float)NPTS);
        red[tid] = p * logf(p + 1e-10f);
        __syncthreads();
        for (int s = 512; s; s >>= 1) {
            if (tid < s) red[tid] += red[tid + s];
            __syncthreads();
        }
        ppl[lvl] = expf(-red[0]);
        __syncthreads();
    }

    if (tid == 0) {
        size_t base = (size_t)2 * NELEM;
        out[base + 0] = loss;
        out[base + 1] = loss;
        out[base + 2] = ppl[0];
        out[base + 3] = ppl[1];
    }
}

// ---------------- launcher ----------------
extern "C" void kernel_launch(void* const* d_in, const int* in_sizes, int n_in,
                              void* d_out, int out_size) {
    const float* h_top  = (const float*)d_in[0];
    const float* h_bot  = (const float*)d_in[1];
    const float* cb_top = (const float*)d_in[2];
    const float* cb_bot = (const float*)d_in[3];
    float* out = (float*)d_out;

    cudaFuncSetAttribute(argmin_kernel,
                         cudaFuncAttributeMaxDynamicSharedMemorySize, ARG_SMEM);

    xsplit_kernel<<<dim3(TLEN / 32, DIM / 64, BATCH * LEVELS), 256>>>(h_top, h_bot);
    ecnorm_kernel<<<dim3(KCODES / 8, LEVELS), 256>>>(cb_top, cb_bot);
    btrans_kernel<<<dim3(KCODES / 32, DIM / 32, LEVELS), 256>>>(cb_top, cb_bot);
    argmin_kernel<<<dim3(NPTS / 64, LEVELS), 256, ARG_SMEM>>>();
    refine_kernel<<<dim3(512, LEVELS), 1024>>>(h_top, h_bot);
    gather_kernel<<<dim3(TLEN / 32, BATCH, LEVELS), 256>>>(h_top, h_bot, cb_top, cb_bot, out);
    finalize_kernel<<<1, 1024>>>(out);
}